// round 10
// baseline (speedup 1.0000x reference)
#include <cuda_runtime.h>
#include <cuda_bf16.h>
#include <math.h>
#include <stdint.h>

#define TOK    4096
#define HID    3584
#define NQH    28
#define NKVH   4
#define HDIM   128
#define SEQL   1024
#define GQA    7
#define QSCALE 0.08838834764831845f   // 1/sqrt(128)
#define NQK    (NQH * HDIM)           // 3584
#define NKVD   (NKVH * HDIM)          // 512
#define NQKV   (NQK + 2 * NKVD)       // 4608

// ---------------- scratch (device globals) ----------------
__device__ float2 g_ropetab[(size_t)TOK * 64];        // (cos, sin) per (t, d)

__device__ __nv_bfloat16 g_hid_hi[(size_t)TOK * HID];
__device__ __nv_bfloat16 g_hid_lo[(size_t)TOK * HID];
__device__ __nv_bfloat16 g_wqkvt_hi[(size_t)NQKV * HID];
__device__ __nv_bfloat16 g_wqkvt_lo[(size_t)NQKV * HID];
__device__ __nv_bfloat16 g_wot_hi[(size_t)HID * NQK];
__device__ __nv_bfloat16 g_wot_lo[(size_t)HID * NQK];

__device__ __nv_bfloat16 g_q_hi[(size_t)TOK * NQK];   // roped+scaled Q
__device__ __nv_bfloat16 g_q_lo[(size_t)TOK * NQK];
__device__ __nv_bfloat16 g_k_hi[(size_t)TOK * NKVD];  // roped K
__device__ __nv_bfloat16 g_k_lo[(size_t)TOK * NKVD];
__device__ __nv_bfloat16 g_v_hi[(size_t)TOK * NKVD];
__device__ __nv_bfloat16 g_v_lo[(size_t)TOK * NKVD];
__device__ __nv_bfloat16 g_att_hi[(size_t)TOK * NQK]; // attention out
__device__ __nv_bfloat16 g_att_lo[(size_t)TOK * NQK];

// ==================== PTX helpers ====================
__device__ __forceinline__ uint32_t smem_to_u32(const void* p) {
    uint32_t a;
    asm("{ .reg .u64 t; cvta.to.shared.u64 t, %1; cvt.u32.u64 %0, t; }" : "=r"(a) : "l"(p));
    return a;
}
#define CP_ASYNC16(dst, src) \
    asm volatile("cp.async.cg.shared.global [%0], [%1], 16;" :: "r"(dst), "l"(src))
#define CP_COMMIT() asm volatile("cp.async.commit_group;" ::: "memory")
#define CP_WAIT1()  asm volatile("cp.async.wait_group 1;" ::: "memory")

#define LDSM4(r, addr) \
    asm volatile("ldmatrix.sync.aligned.m8n8.x4.shared.b16 {%0,%1,%2,%3}, [%4];" \
        : "=r"((r)[0]), "=r"((r)[1]), "=r"((r)[2]), "=r"((r)[3]) : "r"(addr))
#define LDSM4T(r, addr) \
    asm volatile("ldmatrix.sync.aligned.m8n8.x4.trans.shared.b16 {%0,%1,%2,%3}, [%4];" \
        : "=r"((r)[0]), "=r"((r)[1]), "=r"((r)[2]), "=r"((r)[3]) : "r"(addr))

#define MMA16816(d, a, b0, b1) \
    asm volatile("mma.sync.aligned.m16n8k16.row.col.f32.bf16.bf16.f32 " \
        "{%0,%1,%2,%3}, {%4,%5,%6,%7}, {%8,%9}, {%0,%1,%2,%3};" \
        : "+f"((d)[0]), "+f"((d)[1]), "+f"((d)[2]), "+f"((d)[3]) \
        : "r"((a)[0]), "r"((a)[1]), "r"((a)[2]), "r"((a)[3]), "r"(b0), "r"(b1))

__device__ __forceinline__ uint32_t pack_bf16x2(float a, float b) {
    __nv_bfloat162 h = __floats2bfloat162_rn(a, b);
    return *(uint32_t*)&h;
}

// ==================== small kernels ====================
__global__ void build_rope_tab(const int* __restrict__ positions)
{
    const int i = blockIdx.x * blockDim.x + threadIdx.x;
    if (i >= TOK * 64) return;
    const int d = i & 63, t = i >> 6;
    const float inv = exp2f((float)d * -0.31143075693324f);  // theta^(-d/64)
    float sv, cv;
    sincosf((float)positions[t] * inv, &sv, &cv);
    g_ropetab[i] = make_float2(cv, sv);
}

__global__ void split_convert(const float* __restrict__ src,
                              __nv_bfloat16* __restrict__ hi,
                              __nv_bfloat16* __restrict__ lo, int n)
{
    int i = (blockIdx.x * blockDim.x + threadIdx.x) * 4;
    if (i >= n) return;
    float4 v = *(const float4*)(src + i);
    __nv_bfloat16 h0 = __float2bfloat16(v.x), h1 = __float2bfloat16(v.y);
    __nv_bfloat16 h2 = __float2bfloat16(v.z), h3 = __float2bfloat16(v.w);
    __nv_bfloat16 l0 = __float2bfloat16(v.x - __bfloat162float(h0));
    __nv_bfloat16 l1 = __float2bfloat16(v.y - __bfloat162float(h1));
    __nv_bfloat16 l2 = __float2bfloat16(v.z - __bfloat162float(h2));
    __nv_bfloat16 l3 = __float2bfloat16(v.w - __bfloat162float(h3));
    *(__nv_bfloat162*)(hi + i)     = __nv_bfloat162(h0, h1);
    *(__nv_bfloat162*)(hi + i + 2) = __nv_bfloat162(h2, h3);
    *(__nv_bfloat162*)(lo + i)     = __nv_bfloat162(l0, l1);
    *(__nv_bfloat162*)(lo + i + 2) = __nv_bfloat162(l2, l3);
}

// src [R, C] fp32 -> dst [C, R] bf16 hi/lo
__global__ void split_transpose(const float* __restrict__ src,
                                __nv_bfloat16* __restrict__ hi,
                                __nv_bfloat16* __restrict__ lo, int R, int C)
{
    __shared__ float t[32][33];
    const int tx = threadIdx.x & 31;
    const int ty = threadIdx.x >> 5;
    const int r0 = blockIdx.y * 32;
    const int c0 = blockIdx.x * 32;
#pragma unroll
    for (int i = 0; i < 4; i++) {
        int r = ty + 8 * i;
        t[r][tx] = src[(size_t)(r0 + r) * C + c0 + tx];
    }
    __syncthreads();
#pragma unroll
    for (int i = 0; i < 4; i++) {
        int r = ty + 8 * i;
        float x = t[tx][r];
        __nv_bfloat16 h = __float2bfloat16(x);
        __nv_bfloat16 l = __float2bfloat16(x - __bfloat162float(h));
        size_t o = (size_t)(c0 + r) * R + r0 + tx;
        hi[o] = h;
        lo[o] = l;
    }
}

// ==================== QKV GEMM: HMMA bf16x3, 128x256, fused rope epilogue ==========
// 8 warps (2M x 4N), warp tile 64x64, 3-stage. Epilogue: stage fp32 tile in smem,
// apply rope/scale/split per head-pair, write q/k/v hi+lo and kv_fused.
#define G2_AHI 0
#define G2_ALO 8192
#define G2_BHI 16384
#define G2_BLO 32768
#define G2_STAGE 49152
#define G2_SMEM (3 * G2_STAGE)          // 147456; epilogue stage needs 128*264*4 = 135168

__global__ __launch_bounds__(256, 1) void gemm_qkv(
    const __nv_bfloat16* __restrict__ Ahi, const __nv_bfloat16* __restrict__ Alo,
    const __nv_bfloat16* __restrict__ Bhi, const __nv_bfloat16* __restrict__ Blo,
    const float* __restrict__ bq, const float* __restrict__ bk,
    const float* __restrict__ bv, float* __restrict__ kv_out)
{
    extern __shared__ char smem[];
    const uint32_t sb = smem_to_u32(smem);
    const int tid  = threadIdx.x;
    const int wid  = tid >> 5;
    const int lane = tid & 31;
    const int bn   = blockIdx.x * 256;
    const int bm   = blockIdx.y * 128;   // token offset
    const int m0   = (wid >> 2) * 64;
    const int n0   = (wid & 3) * 64;
    const int K    = HID;

    float acc[4][8][4];
#pragma unroll
    for (int i = 0; i < 4; i++)
#pragma unroll
        for (int j = 0; j < 8; j++)
#pragma unroll
            for (int r = 0; r < 4; r++) acc[i][j][r] = 0.f;

    auto load_stage = [&](int ks, int buf) {
        const uint32_t sbase = sb + buf * G2_STAGE;
#pragma unroll
        for (int u = 0; u < 12; u++) {
            const int s = u * 256 + tid;
            const __nv_bfloat16* src;
            uint32_t dbase;
            int r, ch;
            if (s < 1024) {
                const int bsel = s >> 9, idx = s & 511;
                r = idx >> 2; ch = idx & 3;
                src = (bsel ? Alo : Ahi) + (size_t)(bm + r) * K;
                dbase = bsel ? G2_ALO : G2_AHI;
            } else {
                const int t2 = s - 1024;
                const int bsel = t2 >> 10, idx = t2 & 1023;
                r = idx >> 2; ch = idx & 3;
                src = (bsel ? Blo : Bhi) + (size_t)(bn + r) * K;
                dbase = bsel ? G2_BLO : G2_BHI;
            }
            const int chs = ch ^ ((r ^ (r >> 2)) & 3);
            CP_ASYNC16(sbase + dbase + r * 64 + chs * 16, src + ks * 32 + ch * 8);
        }
    };

    auto compute = [&](int buf) {
        const uint32_t st = sb + buf * G2_STAGE;
#pragma unroll
        for (int ks = 0; ks < 2; ks++) {
            uint32_t ah[4][4], al[4][4];
#pragma unroll
            for (int i = 0; i < 4; i++) {
                const int row = m0 + i * 16 + (lane & 15);
                const int ch  = (ks * 2 + (lane >> 4)) ^ ((row ^ (row >> 2)) & 3);
                LDSM4(ah[i], st + G2_AHI + row * 64 + ch * 16);
                LDSM4(al[i], st + G2_ALO + row * 64 + ch * 16);
            }
#pragma unroll
            for (int nb = 0; nb < 4; nb++) {
                const int row = n0 + nb * 16 + ((lane >> 3) & 1) * 8 + (lane & 7);
                const int ch  = (ks * 2 + (lane >> 4)) ^ ((row ^ (row >> 2)) & 3);
                uint32_t bh[4], bl[4];
                LDSM4(bh, st + G2_BHI + row * 64 + ch * 16);
                LDSM4(bl, st + G2_BLO + row * 64 + ch * 16);
#pragma unroll
                for (int i = 0; i < 4; i++) {
                    MMA16816(acc[i][nb * 2],     ah[i], bh[0], bh[2]);
                    MMA16816(acc[i][nb * 2],     ah[i], bl[0], bl[2]);
                    MMA16816(acc[i][nb * 2],     al[i], bh[0], bh[2]);
                    MMA16816(acc[i][nb * 2 + 1], ah[i], bh[1], bh[3]);
                    MMA16816(acc[i][nb * 2 + 1], ah[i], bl[1], bl[3]);
                    MMA16816(acc[i][nb * 2 + 1], al[i], bh[1], bh[3]);
                }
            }
        }
    };

    const int nst = K >> 5;   // 112
    load_stage(0, 0); CP_COMMIT();
    load_stage(1, 1); CP_COMMIT();
    int buf = 0;
    for (int s = 0; s < nst; s++) {
        CP_WAIT1();
        __syncthreads();
        const int np = s + 2;
        if (np < nst) load_stage(np, (buf + 2) % 3);
        CP_COMMIT();
        compute(buf);
        buf = (buf + 1) % 3;
    }

    // -------- fused epilogue: bias + stage fp32 tile, then rope/split/scatter --------
    auto bias_at = [&](int col) -> float {
        if (col < NQK) return bq[col];
        if (col < NQK + NKVD) return bk[col - NQK];
        return bv[col - NQK - NKVD];
    };

    float* stg = (float*)smem;             // [128][264]
    __syncthreads();                       // all pipeline smem reads done
#pragma unroll
    for (int i = 0; i < 4; i++) {
        const int row = m0 + i * 16 + (lane >> 2);
#pragma unroll
        for (int j = 0; j < 8; j++) {
            const int col = n0 + j * 8 + (lane & 3) * 2;
            const float c0 = bias_at(bn + col), c1 = bias_at(bn + col + 1);
            stg[row * 264 + col]           = acc[i][j][0] + c0;
            stg[row * 264 + col + 1]       = acc[i][j][1] + c1;
            stg[(row + 8) * 264 + col]     = acc[i][j][2] + c0;
            stg[(row + 8) * 264 + col + 1] = acc[i][j][3] + c1;
        }
    }
    __syncthreads();

    const int ttype = (bn < NQK) ? 0 : (bn < NQK + NKVD ? 1 : 2);
#pragma unroll 4
    for (int it = 0; it < 64; it++) {
        const int s = it * 256 + tid;
        const int r = s >> 7;            // 0..127
        const int p = s & 127;
        const int h = p >> 6;            // head within tile (0/1)
        const int d = p & 63;
        const int t = bm + r;
        const float x1 = stg[r * 264 + h * 128 + d];
        const float x2 = stg[r * 264 + h * 128 + d + 64];

        if (ttype == 0) {                // Q: rope + scale + split
            const float2 cs = g_ropetab[t * 64 + d];
            const float y1 = (x1 * cs.x - x2 * cs.y) * QSCALE;
            const float y2 = (x2 * cs.x + x1 * cs.y) * QSCALE;
            const size_t o = (size_t)t * NQK + bn + h * 128 + d;
            const __nv_bfloat16 h1 = __float2bfloat16(y1), h2 = __float2bfloat16(y2);
            g_q_hi[o]      = h1;
            g_q_lo[o]      = __float2bfloat16(y1 - __bfloat162float(h1));
            g_q_hi[o + 64] = h2;
            g_q_lo[o + 64] = __float2bfloat16(y2 - __bfloat162float(h2));
        } else if (ttype == 1) {         // K: rope + split + kv_fused
            const float2 cs = g_ropetab[t * 64 + d];
            const float y1 = x1 * cs.x - x2 * cs.y;
            const float y2 = x2 * cs.x + x1 * cs.y;
            const int kh = ((bn - NQK) >> 7) + h;
            const size_t o = (size_t)t * NKVD + kh * 128 + d;
            const __nv_bfloat16 h1 = __float2bfloat16(y1), h2 = __float2bfloat16(y2);
            g_k_hi[o]      = h1;
            g_k_lo[o]      = __float2bfloat16(y1 - __bfloat162float(h1));
            g_k_hi[o + 64] = h2;
            g_k_lo[o + 64] = __float2bfloat16(y2 - __bfloat162float(h2));
            float* dst = kv_out + ((size_t)t * 8 + kh) * 128;
            dst[d]      = y1;
            dst[d + 64] = y2;
        } else {                         // V: split + kv_fused
            const int vh = ((bn - NQK - NKVD) >> 7) + h;
            const size_t o = (size_t)t * NKVD + vh * 128 + d;
            const __nv_bfloat16 h1 = __float2bfloat16(x1), h2 = __float2bfloat16(x2);
            g_v_hi[o]      = h1;
            g_v_lo[o]      = __float2bfloat16(x1 - __bfloat162float(h1));
            g_v_hi[o + 64] = h2;
            g_v_lo[o + 64] = __float2bfloat16(x2 - __bfloat162float(h2));
            float* dst = kv_out + ((size_t)t * 8 + 4 + vh) * 128;
            dst[d]      = x1;
            dst[d + 64] = x2;
        }
    }
}

// ==================== o_proj GEMM: HMMA bf16x3, 128x128, 2 CTAs/SM ====================
#define G1_AHI 0
#define G1_ALO 8192
#define G1_BHI 16384
#define G1_BLO 24576
#define G1_STAGE 32768
#define G1_SMEM (3 * G1_STAGE)

__global__ __launch_bounds__(128, 2) void gemm_hmma128(
    const __nv_bfloat16* __restrict__ Ahi, const __nv_bfloat16* __restrict__ Alo,
    const __nv_bfloat16* __restrict__ Bhi, const __nv_bfloat16* __restrict__ Blo,
    float* __restrict__ C, int N, int K)
{
    extern __shared__ char smem[];
    const uint32_t sb = smem_to_u32(smem);
    const int tid  = threadIdx.x;
    const int wid  = tid >> 5;
    const int lane = tid & 31;
    const int bn   = blockIdx.x * 128;
    const int bm   = blockIdx.y * 128;
    const int m0   = (wid >> 1) * 64;
    const int n0   = (wid & 1) * 64;

    float acc[4][8][4];
#pragma unroll
    for (int i = 0; i < 4; i++)
#pragma unroll
        for (int j = 0; j < 8; j++)
#pragma unroll
            for (int r = 0; r < 4; r++) acc[i][j][r] = 0.f;

    auto load_stage = [&](int ks, int buf) {
        const uint32_t sbase = sb + buf * G1_STAGE;
#pragma unroll
        for (int u = 0; u < 16; u++) {
            const int s     = u * 128 + tid;
            const int which = s >> 9;
            const int idx   = s & 511;
            const int r     = idx >> 2;
            const int ch    = idx & 3;
            const __nv_bfloat16* src;
            if (which == 0)      src = Ahi + (size_t)(bm + r) * K;
            else if (which == 1) src = Alo + (size_t)(bm + r) * K;
            else if (which == 2) src = Bhi + (size_t)(bn + r) * K;
            else                 src = Blo + (size_t)(bn + r) * K;
            const int chs = ch ^ ((r ^ (r >> 2)) & 3);
            CP_ASYNC16(sbase + which * 8192 + r * 64 + chs * 16, src + ks * 32 + ch * 8);
        }
    };

    auto compute = [&](int buf) {
        const uint32_t st = sb + buf * G1_STAGE;
#pragma unroll
        for (int ks = 0; ks < 2; ks++) {
            uint32_t ah[4][4], al[4][4];
#pragma unroll
            for (int i = 0; i < 4; i++) {
                const int row = m0 + i * 16 + (lane & 15);
                const int ch  = (ks * 2 + (lane >> 4)) ^ ((row ^ (row >> 2)) & 3);
                LDSM4(ah[i], st + G1_AHI + row * 64 + ch * 16);
                LDSM4(al[i], st + G1_ALO + row * 64 + ch * 16);
            }
#pragma unroll
            for (int nb = 0; nb < 4; nb++) {
                const int row = n0 + nb * 16 + ((lane >> 3) & 1) * 8 + (lane & 7);
                const int ch  = (ks * 2 + (lane >> 4)) ^ ((row ^ (row >> 2)) & 3);
                uint32_t bh[4], bl[4];
                LDSM4(bh, st + G1_BHI + row * 64 + ch * 16);
                LDSM4(bl, st + G1_BLO + row * 64 + ch * 16);
#pragma unroll
                for (int i = 0; i < 4; i++) {
                    MMA16816(acc[i][nb * 2],     ah[i], bh[0], bh[2]);
                    MMA16816(acc[i][nb * 2],     ah[i], bl[0], bl[2]);
                    MMA16816(acc[i][nb * 2],     al[i], bh[0], bh[2]);
                    MMA16816(acc[i][nb * 2 + 1], ah[i], bh[1], bh[3]);
                    MMA16816(acc[i][nb * 2 + 1], ah[i], bl[1], bl[3]);
                    MMA16816(acc[i][nb * 2 + 1], al[i], bh[1], bh[3]);
                }
            }
        }
    };

    const int nst = K >> 5;
    load_stage(0, 0); CP_COMMIT();
    load_stage(1, 1); CP_COMMIT();
    int buf = 0;
    for (int s = 0; s < nst; s++) {
        CP_WAIT1();
        __syncthreads();
        const int np = s + 2;
        if (np < nst) load_stage(np, (buf + 2) % 3);
        CP_COMMIT();
        compute(buf);
        buf = (buf + 1) % 3;
    }

#pragma unroll
    for (int i = 0; i < 4; i++) {
        const int row = bm + m0 + i * 16 + (lane >> 2);
#pragma unroll
        for (int j = 0; j < 8; j++) {
            const int col = bn + n0 + j * 8 + (lane & 3) * 2;
            float2 v;
            v.x = acc[i][j][0]; v.y = acc[i][j][1];
            *(float2*)(C + (size_t)row * N + col) = v;
            v.x = acc[i][j][2]; v.y = acc[i][j][3];
            *(float2*)(C + (size_t)(row + 8) * N + col) = v;
        }
    }
}

// ==================== HMMA flash attention (double-buffered KV) ====================
#define A_QHI 0
#define A_QLO 32768
#define A_KV  65536
#define A_KVSTAGE 65536
#define A_SMEM (A_KV + 2 * A_KVSTAGE)

__global__ __launch_bounds__(256, 1) void attn_hmma()
{
    extern __shared__ char smem[];
    const uint32_t sb = smem_to_u32(smem);
    const int tid  = threadIdx.x;
    const int wid  = tid >> 5;
    const int lane = tid & 31;
    const int qh   = blockIdx.x;
    const int qt   = (gridDim.y - 1) - blockIdx.y;  // heavy tiles first
    const int b    = blockIdx.z;
    const int kvh  = qh / GQA;
    const int t0   = b * SEQL + qt * 128;

#pragma unroll
    for (int u = 0; u < 16; u++) {
        const int s   = u * 256 + tid;
        const int bsel = s >> 11;
        const int r   = (s >> 4) & 127;
        const int ch  = s & 15;
        const __nv_bfloat16* src =
            (bsel ? g_q_lo : g_q_hi) + (size_t)(t0 + r) * NQK + qh * HDIM + ch * 8;
        CP_ASYNC16(sb + (bsel ? A_QLO : A_QHI) + r * 256 + ((ch ^ (r & 7)) * 16), src);
    }
    CP_COMMIT();

    const int ktmax = 2 * qt + 2;

    auto load_kv = [&](int kt, int buf) {
        const int tk = b * SEQL + kt * 64;
        const uint32_t stb = sb + A_KV + buf * A_KVSTAGE;
#pragma unroll
        for (int u = 0; u < 16; u++) {
            const int s    = u * 256 + tid;
            const int bsel = s >> 10;           // 0:Khi 1:Klo 2:Vhi 3:Vlo
            const int r    = (s >> 4) & 63;
            const int ch   = s & 15;
            const __nv_bfloat16* base =
                (bsel == 0) ? g_k_hi : (bsel == 1) ? g_k_lo : (bsel == 2) ? g_v_hi : g_v_lo;
            const __nv_bfloat16* src = base + (size_t)(tk + r) * NKVD + kvh * HDIM + ch * 8;
            CP_ASYNC16(stb + bsel * 16384 + r * 256 + ((ch ^ (r & 7)) * 16), src);
        }
    };

    load_kv(0, 0);
    CP_COMMIT();

    float m_run[2] = {-1e30f, -1e30f};
    float l_run[2] = {0.f, 0.f};
    float acc[16][4];
#pragma unroll
    for (int nt = 0; nt < 16; nt++)
#pragma unroll
        for (int r = 0; r < 4; r++) acc[nt][r] = 0.f;

    const int arow   = wid * 16 + (lane & 15);
    const int brow_b = ((lane >> 3) & 1) * 8 + (lane & 7);

    for (int kt = 0; kt < ktmax; kt++) {
        __syncthreads();
        if (kt + 1 < ktmax) load_kv(kt + 1, (kt + 1) & 1);
        CP_COMMIT();
        CP_WAIT1();
        __syncthreads();

        const uint32_t stq = sb + A_KV + (kt & 1) * A_KVSTAGE;
        const uint32_t sK  = stq;
        const uint32_t sKl = stq + 16384;
        const uint32_t sV  = stq + 32768;
        const uint32_t sVl = stq + 49152;

        float s_acc[8][4];
#pragma unroll
        for (int nt = 0; nt < 8; nt++)
#pragma unroll
            for (int r = 0; r < 4; r++) s_acc[nt][r] = 0.f;

#pragma unroll
        for (int ks = 0; ks < 8; ks++) {
            uint32_t ah[4], al[4];
            const uint32_t aoff = arow * 256 + (((ks * 2 + (lane >> 4)) ^ (arow & 7)) * 16);
            LDSM4(ah, sb + A_QHI + aoff);
            LDSM4(al, sb + A_QLO + aoff);
#pragma unroll
            for (int nb = 0; nb < 4; nb++) {
                const int brow = nb * 16 + brow_b;
                const uint32_t boff = brow * 256 + (((ks * 2 + (lane >> 4)) ^ (brow & 7)) * 16);
                uint32_t bh[4], bl[4];
                LDSM4(bh, sK  + boff);
                LDSM4(bl, sKl + boff);
                MMA16816(s_acc[nb * 2],     ah, bh[0], bh[2]);
                MMA16816(s_acc[nb * 2],     ah, bl[0], bl[2]);
                MMA16816(s_acc[nb * 2],     al, bh[0], bh[2]);
                MMA16816(s_acc[nb * 2 + 1], ah, bh[1], bh[3]);
                MMA16816(s_acc[nb * 2 + 1], ah, bl[1], bl[3]);
                MMA16816(s_acc[nb * 2 + 1], al, bh[1], bh[3]);
            }
        }

        if (kt >= 2 * qt) {
            const int row0 = qt * 128 + wid * 16 + (lane >> 2);
            const int colb = kt * 64 + (lane & 3) * 2;
#pragma unroll
            for (int nt = 0; nt < 8; nt++) {
                const int c0 = colb + nt * 8;
                if (c0     > row0)     s_acc[nt][0] = -1e30f;
                if (c0 + 1 > row0)     s_acc[nt][1] = -1e30f;
                if (c0     > row0 + 8) s_acc[nt][2] = -1e30f;
                if (c0 + 1 > row0 + 8) s_acc[nt][3] = -1e30f;
            }
        }

        float ml0 = -1e30f, ml1 = -1e30f;
#pragma unroll
        for (int nt = 0; nt < 8; nt++) {
            ml0 = fmaxf(ml0, fmaxf(s_acc[nt][0], s_acc[nt][1]));
            ml1 = fmaxf(ml1, fmaxf(s_acc[nt][2], s_acc[nt][3]));
        }
        ml0 = fmaxf(ml0, __shfl_xor_sync(0xffffffffu, ml0, 1));
        ml0 = fmaxf(ml0, __shfl_xor_sync(0xffffffffu, ml0, 2));
        ml1 = fmaxf(ml1, __shfl_xor_sync(0xffffffffu, ml1, 1));
        ml1 = fmaxf(ml1, __shfl_xor_sync(0xffffffffu, ml1, 2));
        const float mn0 = fmaxf(m_run[0], ml0);
        const float mn1 = fmaxf(m_run[1], ml1);
        const float al0 = __expf(m_run[0] - mn0);
        const float al1 = __expf(m_run[1] - mn1);
        m_run[0] = mn0; m_run[1] = mn1;

        float ps0 = 0.f, ps1 = 0.f;
#pragma unroll
        for (int nt = 0; nt < 8; nt++) {
            s_acc[nt][0] = __expf(s_acc[nt][0] - mn0);
            s_acc[nt][1] = __expf(s_acc[nt][1] - mn0);
            s_acc[nt][2] = __expf(s_acc[nt][2] - mn1);
            s_acc[nt][3] = __expf(s_acc[nt][3] - mn1);
            ps0 += s_acc[nt][0] + s_acc[nt][1];
            ps1 += s_acc[nt][2] + s_acc[nt][3];
        }
        ps0 += __shfl_xor_sync(0xffffffffu, ps0, 1);
        ps0 += __shfl_xor_sync(0xffffffffu, ps0, 2);
        ps1 += __shfl_xor_sync(0xffffffffu, ps1, 1);
        ps1 += __shfl_xor_sync(0xffffffffu, ps1, 2);
        l_run[0] = l_run[0] * al0 + ps0;
        l_run[1] = l_run[1] * al1 + ps1;
#pragma unroll
        for (int nt = 0; nt < 16; nt++) {
            acc[nt][0] *= al0; acc[nt][1] *= al0;
            acc[nt][2] *= al1; acc[nt][3] *= al1;
        }

        uint32_t pa_h[4][4], pa_l[4][4];
#pragma unroll
        for (int s2 = 0; s2 < 4; s2++) {
            float* e = s_acc[2 * s2];
            float* o = s_acc[2 * s2 + 1];
            pa_h[s2][0] = pack_bf16x2(e[0], e[1]);
            pa_h[s2][1] = pack_bf16x2(e[2], e[3]);
            pa_h[s2][2] = pack_bf16x2(o[0], o[1]);
            pa_h[s2][3] = pack_bf16x2(o[2], o[3]);
#pragma unroll
            for (int q2 = 0; q2 < 4; q2++) {
                float r0 = (q2 < 2 ? e : o)[(q2 & 1) * 2];
                float r1 = (q2 < 2 ? e : o)[(q2 & 1) * 2 + 1];
                __nv_bfloat162* hh = (__nv_bfloat162*)&pa_h[s2][q2];
                pa_l[s2][q2] = pack_bf16x2(r0 - __bfloat162float(hh->x),
                                           r1 - __bfloat162float(hh->y));
            }
        }

#pragma unroll
        for (int s2 = 0; s2 < 4; s2++) {
            const int vrow = s2 * 16 + brow_b;
#pragma unroll
            for (int np = 0; np < 8; np++) {
                const uint32_t voff = vrow * 256 + (((np * 2 + (lane >> 4)) ^ (vrow & 7)) * 16);
                uint32_t vh[4], vl[4];
                LDSM4T(vh, sV  + voff);
                LDSM4T(vl, sVl + voff);
                MMA16816(acc[np * 2],     pa_h[s2], vh[0], vh[1]);
                MMA16816(acc[np * 2],     pa_h[s2], vl[0], vl[1]);
                MMA16816(acc[np * 2],     pa_l[s2], vh[0], vh[1]);
                MMA16816(acc[np * 2 + 1], pa_h[s2], vh[2], vh[3]);
                MMA16816(acc[np * 2 + 1], pa_h[s2], vl[2], vl[3]);
                MMA16816(acc[np * 2 + 1], pa_l[s2], vh[2], vh[3]);
            }
        }
    }

    const float il0 = 1.f / l_run[0];
    const float il1 = 1.f / l_run[1];
    const int row0 = t0 + wid * 16 + (lane >> 2);
#pragma unroll
    for (int nt = 0; nt < 16; nt++) {
        const int col = qh * HDIM + nt * 8 + (lane & 3) * 2;
        float o0 = acc[nt][0] * il0, o1 = acc[nt][1] * il0;
        float o2 = acc[nt][2] * il1, o3 = acc[nt][3] * il1;
        uint32_t h01 = pack_bf16x2(o0, o1);
        uint32_t h23 = pack_bf16x2(o2, o3);
        __nv_bfloat162* p01 = (__nv_bfloat162*)&h01;
        __nv_bfloat162* p23 = (__nv_bfloat162*)&h23;
        uint32_t l01 = pack_bf16x2(o0 - __bfloat162float(p01->x), o1 - __bfloat162float(p01->y));
        uint32_t l23 = pack_bf16x2(o2 - __bfloat162float(p23->x), o3 - __bfloat162float(p23->y));
        *(uint32_t*)(g_att_hi + (size_t)row0 * NQK + col)       = h01;
        *(uint32_t*)(g_att_lo + (size_t)row0 * NQK + col)       = l01;
        *(uint32_t*)(g_att_hi + (size_t)(row0 + 8) * NQK + col) = h23;
        *(uint32_t*)(g_att_lo + (size_t)(row0 + 8) * NQK + col) = l23;
    }
}

// ---------------- launch ----------------
extern "C" void kernel_launch(void* const* d_in, const int* in_sizes, int n_in,
                              void* d_out, int out_size)
{
    const float* hidden    = (const float*)d_in[0];
    const int*   positions = (const int*)  d_in[1];
    const float* wq        = (const float*)d_in[2];
    const float* bq        = (const float*)d_in[3];
    const float* wk        = (const float*)d_in[4];
    const float* bk        = (const float*)d_in[5];
    const float* wv        = (const float*)d_in[6];
    const float* bv        = (const float*)d_in[7];
    const float* wo        = (const float*)d_in[8];
    (void)in_sizes; (void)n_in; (void)out_size;

    float* out    = (float*)d_out;                 // [T, HID]
    float* out_kv = out + (size_t)TOK * HID;       // [T, 8, 128]

    __nv_bfloat16 *hid_hi, *hid_lo, *wqkvt_hi, *wqkvt_lo, *wot_hi, *wot_lo, *att_hi, *att_lo;
    cudaGetSymbolAddress((void**)&hid_hi,   g_hid_hi);
    cudaGetSymbolAddress((void**)&hid_lo,   g_hid_lo);
    cudaGetSymbolAddress((void**)&wqkvt_hi, g_wqkvt_hi);
    cudaGetSymbolAddress((void**)&wqkvt_lo, g_wqkvt_lo);
    cudaGetSymbolAddress((void**)&wot_hi,   g_wot_hi);
    cudaGetSymbolAddress((void**)&wot_lo,   g_wot_lo);
    cudaGetSymbolAddress((void**)&att_hi,   g_att_hi);
    cudaGetSymbolAddress((void**)&att_lo,   g_att_lo);

    cudaFuncSetAttribute(gemm_qkv,     cudaFuncAttributeMaxDynamicSharedMemorySize, G2_SMEM);
    cudaFuncSetAttribute(gemm_hmma128, cudaFuncAttributeMaxDynamicSharedMemorySize, G1_SMEM);
    cudaFuncSetAttribute(attn_hmma,    cudaFuncAttributeMaxDynamicSharedMemorySize, A_SMEM);

    // rope table + conversions
    build_rope_tab<<<(TOK * 64 + 255) / 256, 256>>>(positions);
    split_convert<<<(TOK * HID / 4 + 255) / 256, 256>>>(hidden, hid_hi, hid_lo, TOK * HID);
    split_transpose<<<dim3(NQK / 32,  HID / 32), 256>>>(wq, wqkvt_hi, wqkvt_lo, HID, NQK);
    split_transpose<<<dim3(NKVD / 32, HID / 32), 256>>>(
        wk, wqkvt_hi + (size_t)NQK * HID, wqkvt_lo + (size_t)NQK * HID, HID, NKVD);
    split_transpose<<<dim3(NKVD / 32, HID / 32), 256>>>(
        wv, wqkvt_hi + (size_t)(NQK + NKVD) * HID, wqkvt_lo + (size_t)(NQK + NKVD) * HID, HID, NKVD);
    split_transpose<<<dim3(HID / 32, NQK / 32), 256>>>(wo, wot_hi, wot_lo, NQK, HID);

    // fused QKV projection + bias + rope + split + kv_fused scatter
    gemm_qkv<<<dim3(NQKV / 256, TOK / 128), 256, G2_SMEM>>>(
        hid_hi, hid_lo, wqkvt_hi, wqkvt_lo, bq, bk, bv, out_kv);

    // HMMA flash attention (double-buffered KV)
    attn_hmma<<<dim3(NQH, SEQL / 128, 4), 256, A_SMEM>>>();

    // o_proj: 128x128 tiles, 2 CTAs/SM
    gemm_hmma128<<<dim3(HID / 128, TOK / 128), 128, G1_SMEM>>>(
        att_hi, att_lo, wot_hi, wot_lo, out, HID, NQK);
}

// round 13
// speedup vs baseline: 1.0264x; 1.0264x over previous
#include <cuda_runtime.h>
#include <cuda_bf16.h>
#include <math.h>
#include <stdint.h>

#define TOK    4096
#define HID    3584
#define NQH    28
#define NKVH   4
#define HDIM   128
#define SEQL   1024
#define GQA    7
#define QSCALE 0.08838834764831845f   // 1/sqrt(128)
#define NQK    (NQH * HDIM)           // 3584
#define NKVD   (NKVH * HDIM)          // 512
#define NQKV   (NQK + 2 * NKVD)       // 4608

// ---------------- scratch (device globals) ----------------
__device__ float g_qkv[(size_t)TOK * NQKV];     // fused QKV projection output (fp32)

__device__ __nv_bfloat16 g_hid_hi[(size_t)TOK * HID];
__device__ __nv_bfloat16 g_hid_lo[(size_t)TOK * HID];
__device__ __nv_bfloat16 g_wqkvt_hi[(size_t)NQKV * HID];
__device__ __nv_bfloat16 g_wqkvt_lo[(size_t)NQKV * HID];
__device__ __nv_bfloat16 g_wot_hi[(size_t)HID * NQK];
__device__ __nv_bfloat16 g_wot_lo[(size_t)HID * NQK];

__device__ __nv_bfloat16 g_q_hi[(size_t)TOK * NQK];   // roped+scaled Q
__device__ __nv_bfloat16 g_q_lo[(size_t)TOK * NQK];
__device__ __nv_bfloat16 g_k_hi[(size_t)TOK * NKVD];  // roped K
__device__ __nv_bfloat16 g_k_lo[(size_t)TOK * NKVD];
__device__ __nv_bfloat16 g_v_hi[(size_t)TOK * NKVD];
__device__ __nv_bfloat16 g_v_lo[(size_t)TOK * NKVD];
__device__ __nv_bfloat16 g_att_hi[(size_t)TOK * NQK]; // attention out
__device__ __nv_bfloat16 g_att_lo[(size_t)TOK * NQK];

// ==================== PTX helpers ====================
__device__ __forceinline__ uint32_t smem_to_u32(const void* p) {
    uint32_t a;
    asm("{ .reg .u64 t; cvta.to.shared.u64 t, %1; cvt.u32.u64 %0, t; }" : "=r"(a) : "l"(p));
    return a;
}
#define CP_ASYNC16(dst, src) \
    asm volatile("cp.async.cg.shared.global [%0], [%1], 16;" :: "r"(dst), "l"(src))
#define CP_COMMIT() asm volatile("cp.async.commit_group;" ::: "memory")
#define CP_WAIT1()  asm volatile("cp.async.wait_group 1;" ::: "memory")

#define LDSM4(r, addr) \
    asm volatile("ldmatrix.sync.aligned.m8n8.x4.shared.b16 {%0,%1,%2,%3}, [%4];" \
        : "=r"((r)[0]), "=r"((r)[1]), "=r"((r)[2]), "=r"((r)[3]) : "r"(addr))
#define LDSM4T(r, addr) \
    asm volatile("ldmatrix.sync.aligned.m8n8.x4.trans.shared.b16 {%0,%1,%2,%3}, [%4];" \
        : "=r"((r)[0]), "=r"((r)[1]), "=r"((r)[2]), "=r"((r)[3]) : "r"(addr))

#define MMA16816(d, a, b0, b1) \
    asm volatile("mma.sync.aligned.m16n8k16.row.col.f32.bf16.bf16.f32 " \
        "{%0,%1,%2,%3}, {%4,%5,%6,%7}, {%8,%9}, {%0,%1,%2,%3};" \
        : "+f"((d)[0]), "+f"((d)[1]), "+f"((d)[2]), "+f"((d)[3]) \
        : "r"((a)[0]), "r"((a)[1]), "r"((a)[2]), "r"((a)[3]), "r"(b0), "r"(b1))

__device__ __forceinline__ uint32_t pack_bf16x2(float a, float b) {
    __nv_bfloat162 h = __floats2bfloat162_rn(a, b);
    return *(uint32_t*)&h;
}

// ==================== split/convert kernels ====================
__global__ void split_convert(const float* __restrict__ src,
                              __nv_bfloat16* __restrict__ hi,
                              __nv_bfloat16* __restrict__ lo, int n)
{
    int i = (blockIdx.x * blockDim.x + threadIdx.x) * 4;
    if (i >= n) return;
    float4 v = *(const float4*)(src + i);
    __nv_bfloat16 h0 = __float2bfloat16(v.x), h1 = __float2bfloat16(v.y);
    __nv_bfloat16 h2 = __float2bfloat16(v.z), h3 = __float2bfloat16(v.w);
    __nv_bfloat16 l0 = __float2bfloat16(v.x - __bfloat162float(h0));
    __nv_bfloat16 l1 = __float2bfloat16(v.y - __bfloat162float(h1));
    __nv_bfloat16 l2 = __float2bfloat16(v.z - __bfloat162float(h2));
    __nv_bfloat16 l3 = __float2bfloat16(v.w - __bfloat162float(h3));
    *(__nv_bfloat162*)(hi + i)     = __nv_bfloat162(h0, h1);
    *(__nv_bfloat162*)(hi + i + 2) = __nv_bfloat162(h2, h3);
    *(__nv_bfloat162*)(lo + i)     = __nv_bfloat162(l0, l1);
    *(__nv_bfloat162*)(lo + i + 2) = __nv_bfloat162(l2, l3);
}

// src [R, C] fp32 -> dst [C, R] bf16 hi/lo
__global__ void split_transpose(const float* __restrict__ src,
                                __nv_bfloat16* __restrict__ hi,
                                __nv_bfloat16* __restrict__ lo, int R, int C)
{
    __shared__ float t[32][33];
    const int tx = threadIdx.x & 31;
    const int ty = threadIdx.x >> 5;
    const int r0 = blockIdx.y * 32;
    const int c0 = blockIdx.x * 32;
#pragma unroll
    for (int i = 0; i < 4; i++) {
        int r = ty + 8 * i;
        t[r][tx] = src[(size_t)(r0 + r) * C + c0 + tx];
    }
    __syncthreads();
#pragma unroll
    for (int i = 0; i < 4; i++) {
        int r = ty + 8 * i;
        float x = t[tx][r];
        __nv_bfloat16 h = __float2bfloat16(x);
        __nv_bfloat16 l = __float2bfloat16(x - __bfloat162float(h));
        size_t o = (size_t)(c0 + r) * R + r0 + tx;
        hi[o] = h;
        lo[o] = l;
    }
}

// ==================== HMMA bf16x3 GEMM, 128x256 tile, 3-stage ====================
// C[M,N] = A[M,K]*B[N,K]^T (+bias). 8 warps (2M x 4N), warp tile 64x64.
#define G2_AHI 0
#define G2_ALO 8192
#define G2_BHI 16384
#define G2_BLO 32768
#define G2_STAGE 49152
#define G2_SMEM (3 * G2_STAGE)

// BMODE: 0 = no bias, 1 = concat bias (b0: NQK, b1: NKVD, b2: NKVD)
template <int BMODE>
__global__ __launch_bounds__(256, 1) void gemm_hmma256(
    const __nv_bfloat16* __restrict__ Ahi, const __nv_bfloat16* __restrict__ Alo,
    const __nv_bfloat16* __restrict__ Bhi, const __nv_bfloat16* __restrict__ Blo,
    const float* __restrict__ b0, const float* __restrict__ b1,
    const float* __restrict__ b2, float* __restrict__ C, int N, int K)
{
    extern __shared__ char smem[];
    const uint32_t sb = smem_to_u32(smem);
    const int tid  = threadIdx.x;
    const int wid  = tid >> 5;
    const int lane = tid & 31;
    const int bn   = blockIdx.x * 256;
    const int bm   = blockIdx.y * 128;
    const int m0   = (wid >> 2) * 64;
    const int n0   = (wid & 3) * 64;

    float acc[4][8][4];
#pragma unroll
    for (int i = 0; i < 4; i++)
#pragma unroll
        for (int j = 0; j < 8; j++)
#pragma unroll
            for (int r = 0; r < 4; r++) acc[i][j][r] = 0.f;

    auto load_stage = [&](int ks, int buf) {
        const uint32_t sbase = sb + buf * G2_STAGE;
#pragma unroll
        for (int u = 0; u < 12; u++) {
            const int s = u * 256 + tid;
            const __nv_bfloat16* src;
            uint32_t dbase;
            int r, ch;
            if (s < 1024) {
                const int bsel = s >> 9, idx = s & 511;
                r = idx >> 2; ch = idx & 3;
                src = (bsel ? Alo : Ahi) + (size_t)(bm + r) * K;
                dbase = bsel ? G2_ALO : G2_AHI;
            } else {
                const int t2 = s - 1024;
                const int bsel = t2 >> 10, idx = t2 & 1023;
                r = idx >> 2; ch = idx & 3;
                src = (bsel ? Blo : Bhi) + (size_t)(bn + r) * K;
                dbase = bsel ? G2_BLO : G2_BHI;
            }
            const int chs = ch ^ ((r ^ (r >> 2)) & 3);
            CP_ASYNC16(sbase + dbase + r * 64 + chs * 16, src + ks * 32 + ch * 8);
        }
    };

    auto compute = [&](int buf) {
        const uint32_t st = sb + buf * G2_STAGE;
#pragma unroll
        for (int ks = 0; ks < 2; ks++) {
            uint32_t ah[4][4], al[4][4];
#pragma unroll
            for (int i = 0; i < 4; i++) {
                const int row = m0 + i * 16 + (lane & 15);
                const int ch  = (ks * 2 + (lane >> 4)) ^ ((row ^ (row >> 2)) & 3);
                LDSM4(ah[i], st + G2_AHI + row * 64 + ch * 16);
                LDSM4(al[i], st + G2_ALO + row * 64 + ch * 16);
            }
#pragma unroll
            for (int nb = 0; nb < 4; nb++) {
                const int row = n0 + nb * 16 + ((lane >> 3) & 1) * 8 + (lane & 7);
                const int ch  = (ks * 2 + (lane >> 4)) ^ ((row ^ (row >> 2)) & 3);
                uint32_t bh[4], bl[4];
                LDSM4(bh, st + G2_BHI + row * 64 + ch * 16);
                LDSM4(bl, st + G2_BLO + row * 64 + ch * 16);
#pragma unroll
                for (int i = 0; i < 4; i++) {
                    MMA16816(acc[i][nb * 2],     ah[i], bh[0], bh[2]);
                    MMA16816(acc[i][nb * 2],     ah[i], bl[0], bl[2]);
                    MMA16816(acc[i][nb * 2],     al[i], bh[0], bh[2]);
                    MMA16816(acc[i][nb * 2 + 1], ah[i], bh[1], bh[3]);
                    MMA16816(acc[i][nb * 2 + 1], ah[i], bl[1], bl[3]);
                    MMA16816(acc[i][nb * 2 + 1], al[i], bh[1], bh[3]);
                }
            }
        }
    };

    const int nst = K >> 5;
    load_stage(0, 0); CP_COMMIT();
    load_stage(1, 1); CP_COMMIT();
    int buf = 0;
    for (int s = 0; s < nst; s++) {
        CP_WAIT1();
        __syncthreads();
        const int np = s + 2;
        if (np < nst) load_stage(np, (buf + 2) % 3);
        CP_COMMIT();
        compute(buf);
        buf = (buf + 1) % 3;
    }

    auto bias_at = [&](int col) -> float {
        if (BMODE == 0) return 0.f;
        if (col < NQK) return b0[col];
        if (col < NQK + NKVD) return b1[col - NQK];
        return b2[col - NQK - NKVD];
    };
#pragma unroll
    for (int i = 0; i < 4; i++) {
        const int row = bm + m0 + i * 16 + (lane >> 2);
#pragma unroll
        for (int j = 0; j < 8; j++) {
            const int col = bn + n0 + j * 8 + (lane & 3) * 2;
            const float c0 = bias_at(col), c1 = bias_at(col + 1);
            float2 v;
            v.x = acc[i][j][0] + c0; v.y = acc[i][j][1] + c1;
            *(float2*)(C + (size_t)row * N + col) = v;
            v.x = acc[i][j][2] + c0; v.y = acc[i][j][3] + c1;
            *(float2*)(C + (size_t)(row + 8) * N + col) = v;
        }
    }
}

// ==================== HMMA bf16x3 GEMM, 128x128 tile, 2 CTAs/SM ====================
// 4 warps (2M x 2N), warp tile 64x64. stage: 4 x 8KB = 32KB; x3 = 96KB.
#define G1_AHI 0
#define G1_ALO 8192
#define G1_BHI 16384
#define G1_BLO 24576
#define G1_STAGE 32768
#define G1_SMEM (3 * G1_STAGE)

__global__ __launch_bounds__(128, 2) void gemm_hmma128(
    const __nv_bfloat16* __restrict__ Ahi, const __nv_bfloat16* __restrict__ Alo,
    const __nv_bfloat16* __restrict__ Bhi, const __nv_bfloat16* __restrict__ Blo,
    float* __restrict__ C, int N, int K)
{
    extern __shared__ char smem[];
    const uint32_t sb = smem_to_u32(smem);
    const int tid  = threadIdx.x;
    const int wid  = tid >> 5;
    const int lane = tid & 31;
    const int bn   = blockIdx.x * 128;
    const int bm   = blockIdx.y * 128;
    const int m0   = (wid >> 1) * 64;
    const int n0   = (wid & 1) * 64;

    float acc[4][8][4];
#pragma unroll
    for (int i = 0; i < 4; i++)
#pragma unroll
        for (int j = 0; j < 8; j++)
#pragma unroll
            for (int r = 0; r < 4; r++) acc[i][j][r] = 0.f;

    // 2048 chunks per stage / 128 threads = 16 each
    auto load_stage = [&](int ks, int buf) {
        const uint32_t sbase = sb + buf * G1_STAGE;
#pragma unroll
        for (int u = 0; u < 16; u++) {
            const int s     = u * 128 + tid;
            const int which = s >> 9;            // 0:Ahi 1:Alo 2:Bhi 3:Blo
            const int idx   = s & 511;
            const int r     = idx >> 2;
            const int ch    = idx & 3;
            const __nv_bfloat16* src;
            if (which == 0)      src = Ahi + (size_t)(bm + r) * K;
            else if (which == 1) src = Alo + (size_t)(bm + r) * K;
            else if (which == 2) src = Bhi + (size_t)(bn + r) * K;
            else                 src = Blo + (size_t)(bn + r) * K;
            const int chs = ch ^ ((r ^ (r >> 2)) & 3);
            CP_ASYNC16(sbase + which * 8192 + r * 64 + chs * 16, src + ks * 32 + ch * 8);
        }
    };

    auto compute = [&](int buf) {
        const uint32_t st = sb + buf * G1_STAGE;
#pragma unroll
        for (int ks = 0; ks < 2; ks++) {
            uint32_t ah[4][4], al[4][4];
#pragma unroll
            for (int i = 0; i < 4; i++) {
                const int row = m0 + i * 16 + (lane & 15);
                const int ch  = (ks * 2 + (lane >> 4)) ^ ((row ^ (row >> 2)) & 3);
                LDSM4(ah[i], st + G1_AHI + row * 64 + ch * 16);
                LDSM4(al[i], st + G1_ALO + row * 64 + ch * 16);
            }
#pragma unroll
            for (int nb = 0; nb < 4; nb++) {
                const int row = n0 + nb * 16 + ((lane >> 3) & 1) * 8 + (lane & 7);
                const int ch  = (ks * 2 + (lane >> 4)) ^ ((row ^ (row >> 2)) & 3);
                uint32_t bh[4], bl[4];
                LDSM4(bh, st + G1_BHI + row * 64 + ch * 16);
                LDSM4(bl, st + G1_BLO + row * 64 + ch * 16);
#pragma unroll
                for (int i = 0; i < 4; i++) {
                    MMA16816(acc[i][nb * 2],     ah[i], bh[0], bh[2]);
                    MMA16816(acc[i][nb * 2],     ah[i], bl[0], bl[2]);
                    MMA16816(acc[i][nb * 2],     al[i], bh[0], bh[2]);
                    MMA16816(acc[i][nb * 2 + 1], ah[i], bh[1], bh[3]);
                    MMA16816(acc[i][nb * 2 + 1], ah[i], bl[1], bl[3]);
                    MMA16816(acc[i][nb * 2 + 1], al[i], bh[1], bh[3]);
                }
            }
        }
    };

    const int nst = K >> 5;
    load_stage(0, 0); CP_COMMIT();
    load_stage(1, 1); CP_COMMIT();
    int buf = 0;
    for (int s = 0; s < nst; s++) {
        CP_WAIT1();
        __syncthreads();
        const int np = s + 2;
        if (np < nst) load_stage(np, (buf + 2) % 3);
        CP_COMMIT();
        compute(buf);
        buf = (buf + 1) % 3;
    }

#pragma unroll
    for (int i = 0; i < 4; i++) {
        const int row = bm + m0 + i * 16 + (lane >> 2);
#pragma unroll
        for (int j = 0; j < 8; j++) {
            const int col = bn + n0 + j * 8 + (lane & 3) * 2;
            float2 v;
            v.x = acc[i][j][0]; v.y = acc[i][j][1];
            *(float2*)(C + (size_t)row * N + col) = v;
            v.x = acc[i][j][2]; v.y = acc[i][j][3];
            *(float2*)(C + (size_t)(row + 8) * N + col) = v;
        }
    }
}

// ---------------- RoPE + kv_fused scatter + bf16 split ----------------
__global__ void rope_scatter(const int* __restrict__ positions,
                             float* __restrict__ kv_out)
{
    const int idx = blockIdx.x * blockDim.x + threadIdx.x;
    if (idx >= TOK * 64) return;
    const int d = idx & 63;
    const int t = idx >> 6;
    const int pos = positions[t];
    const float inv = exp2f((float)d * -0.31143075693324f);  // theta^(-d/64)
    float sv, cv;
    sincosf((float)pos * inv, &sv, &cv);

    const float* row = g_qkv + (size_t)t * NQKV;

    const size_t qb = (size_t)t * NQK;
#pragma unroll 4
    for (int h = 0; h < NQH; h++) {
        const float x1 = row[h * HDIM + d], x2 = row[h * HDIM + d + 64];
        const float y1 = (x1 * cv - x2 * sv) * QSCALE;
        const float y2 = (x2 * cv + x1 * sv) * QSCALE;
        const __nv_bfloat16 h1 = __float2bfloat16(y1), h2 = __float2bfloat16(y2);
        g_q_hi[qb + h * HDIM + d]      = h1;
        g_q_lo[qb + h * HDIM + d]      = __float2bfloat16(y1 - __bfloat162float(h1));
        g_q_hi[qb + h * HDIM + d + 64] = h2;
        g_q_lo[qb + h * HDIM + d + 64] = __float2bfloat16(y2 - __bfloat162float(h2));
    }

    const size_t kb = (size_t)t * NKVD;
#pragma unroll
    for (int kh = 0; kh < NKVH; kh++) {
        const float x1 = row[NQK + kh * HDIM + d], x2 = row[NQK + kh * HDIM + d + 64];
        const float y1 = x1 * cv - x2 * sv;
        const float y2 = x2 * cv + x1 * sv;
        float* dst = kv_out + ((size_t)t * 8 + kh) * HDIM;
        dst[d] = y1; dst[d + 64] = y2;
        const __nv_bfloat16 h1 = __float2bfloat16(y1), h2 = __float2bfloat16(y2);
        g_k_hi[kb + kh * HDIM + d]      = h1;
        g_k_lo[kb + kh * HDIM + d]      = __float2bfloat16(y1 - __bfloat162float(h1));
        g_k_hi[kb + kh * HDIM + d + 64] = h2;
        g_k_lo[kb + kh * HDIM + d + 64] = __float2bfloat16(y2 - __bfloat162float(h2));
    }
#pragma unroll
    for (int vh = 0; vh < NKVH; vh++) {
        const float x1 = row[NQK + NKVD + vh * HDIM + d];
        const float x2 = row[NQK + NKVD + vh * HDIM + d + 64];
        float* dst = kv_out + ((size_t)t * 8 + 4 + vh) * HDIM;
        dst[d] = x1; dst[d + 64] = x2;
        const __nv_bfloat16 h1 = __float2bfloat16(x1), h2 = __float2bfloat16(x2);
        g_v_hi[kb + vh * HDIM + d]      = h1;
        g_v_lo[kb + vh * HDIM + d]      = __float2bfloat16(x1 - __bfloat162float(h1));
        g_v_hi[kb + vh * HDIM + d + 64] = h2;
        g_v_lo[kb + vh * HDIM + d + 64] = __float2bfloat16(x2 - __bfloat162float(h2));
    }
}

// ==================== HMMA flash attention (double-buffered KV) ====================
#define A_QHI 0
#define A_QLO 32768
#define A_KV  65536
#define A_KVSTAGE 65536
#define A_SMEM (A_KV + 2 * A_KVSTAGE)

__global__ __launch_bounds__(256, 1) void attn_hmma()
{
    extern __shared__ char smem[];
    const uint32_t sb = smem_to_u32(smem);
    const int tid  = threadIdx.x;
    const int wid  = tid >> 5;
    const int lane = tid & 31;
    const int qh   = blockIdx.x;
    const int qt   = (gridDim.y - 1) - blockIdx.y;  // heavy tiles first
    const int b    = blockIdx.z;
    const int kvh  = qh / GQA;
    const int t0   = b * SEQL + qt * 128;

#pragma unroll
    for (int u = 0; u < 16; u++) {
        const int s   = u * 256 + tid;
        const int bsel = s >> 11;
        const int r   = (s >> 4) & 127;
        const int ch  = s & 15;
        const __nv_bfloat16* src =
            (bsel ? g_q_lo : g_q_hi) + (size_t)(t0 + r) * NQK + qh * HDIM + ch * 8;
        CP_ASYNC16(sb + (bsel ? A_QLO : A_QHI) + r * 256 + ((ch ^ (r & 7)) * 16), src);
    }
    CP_COMMIT();

    const int ktmax = 2 * qt + 2;

    auto load_kv = [&](int kt, int buf) {
        const int tk = b * SEQL + kt * 64;
        const uint32_t stb = sb + A_KV + buf * A_KVSTAGE;
#pragma unroll
        for (int u = 0; u < 16; u++) {
            const int s    = u * 256 + tid;
            const int bsel = s >> 10;           // 0:Khi 1:Klo 2:Vhi 3:Vlo
            const int r    = (s >> 4) & 63;
            const int ch   = s & 15;
            const __nv_bfloat16* base =
                (bsel == 0) ? g_k_hi : (bsel == 1) ? g_k_lo : (bsel == 2) ? g_v_hi : g_v_lo;
            const __nv_bfloat16* src = base + (size_t)(tk + r) * NKVD + kvh * HDIM + ch * 8;
            CP_ASYNC16(stb + bsel * 16384 + r * 256 + ((ch ^ (r & 7)) * 16), src);
        }
    };

    load_kv(0, 0);
    CP_COMMIT();

    float m_run[2] = {-1e30f, -1e30f};
    float l_run[2] = {0.f, 0.f};
    float acc[16][4];
#pragma unroll
    for (int nt = 0; nt < 16; nt++)
#pragma unroll
        for (int r = 0; r < 4; r++) acc[nt][r] = 0.f;

    const int arow   = wid * 16 + (lane & 15);
    const int brow_b = ((lane >> 3) & 1) * 8 + (lane & 7);

    for (int kt = 0; kt < ktmax; kt++) {
        __syncthreads();
        if (kt + 1 < ktmax) load_kv(kt + 1, (kt + 1) & 1);
        CP_COMMIT();
        CP_WAIT1();
        __syncthreads();

        const uint32_t stq = sb + A_KV + (kt & 1) * A_KVSTAGE;
        const uint32_t sK  = stq;
        const uint32_t sKl = stq + 16384;
        const uint32_t sV  = stq + 32768;
        const uint32_t sVl = stq + 49152;

        float s_acc[8][4];
#pragma unroll
        for (int nt = 0; nt < 8; nt++)
#pragma unroll
            for (int r = 0; r < 4; r++) s_acc[nt][r] = 0.f;

#pragma unroll
        for (int ks = 0; ks < 8; ks++) {
            uint32_t ah[4], al[4];
            const uint32_t aoff = arow * 256 + (((ks * 2 + (lane >> 4)) ^ (arow & 7)) * 16);
            LDSM4(ah, sb + A_QHI + aoff);
            LDSM4(al, sb + A_QLO + aoff);
#pragma unroll
            for (int nb = 0; nb < 4; nb++) {
                const int brow = nb * 16 + brow_b;
                const uint32_t boff = brow * 256 + (((ks * 2 + (lane >> 4)) ^ (brow & 7)) * 16);
                uint32_t bh[4], bl[4];
                LDSM4(bh, sK  + boff);
                LDSM4(bl, sKl + boff);
                MMA16816(s_acc[nb * 2],     ah, bh[0], bh[2]);
                MMA16816(s_acc[nb * 2],     ah, bl[0], bl[2]);
                MMA16816(s_acc[nb * 2],     al, bh[0], bh[2]);
                MMA16816(s_acc[nb * 2 + 1], ah, bh[1], bh[3]);
                MMA16816(s_acc[nb * 2 + 1], ah, bl[1], bl[3]);
                MMA16816(s_acc[nb * 2 + 1], al, bh[1], bh[3]);
            }
        }

        if (kt >= 2 * qt) {
            const int row0 = qt * 128 + wid * 16 + (lane >> 2);
            const int colb = kt * 64 + (lane & 3) * 2;
#pragma unroll
            for (int nt = 0; nt < 8; nt++) {
                const int c0 = colb + nt * 8;
                if (c0     > row0)     s_acc[nt][0] = -1e30f;
                if (c0 + 1 > row0)     s_acc[nt][1] = -1e30f;
                if (c0     > row0 + 8) s_acc[nt][2] = -1e30f;
                if (c0 + 1 > row0 + 8) s_acc[nt][3] = -1e30f;
            }
        }

        float ml0 = -1e30f, ml1 = -1e30f;
#pragma unroll
        for (int nt = 0; nt < 8; nt++) {
            ml0 = fmaxf(ml0, fmaxf(s_acc[nt][0], s_acc[nt][1]));
            ml1 = fmaxf(ml1, fmaxf(s_acc[nt][2], s_acc[nt][3]));
        }
        ml0 = fmaxf(ml0, __shfl_xor_sync(0xffffffffu, ml0, 1));
        ml0 = fmaxf(ml0, __shfl_xor_sync(0xffffffffu, ml0, 2));
        ml1 = fmaxf(ml1, __shfl_xor_sync(0xffffffffu, ml1, 1));
        ml1 = fmaxf(ml1, __shfl_xor_sync(0xffffffffu, ml1, 2));
        const float mn0 = fmaxf(m_run[0], ml0);
        const float mn1 = fmaxf(m_run[1], ml1);
        const float al0 = __expf(m_run[0] - mn0);
        const float al1 = __expf(m_run[1] - mn1);
        m_run[0] = mn0; m_run[1] = mn1;

        float ps0 = 0.f, ps1 = 0.f;
#pragma unroll
        for (int nt = 0; nt < 8; nt++) {
            s_acc[nt][0] = __expf(s_acc[nt][0] - mn0);
            s_acc[nt][1] = __expf(s_acc[nt][1] - mn0);
            s_acc[nt][2] = __expf(s_acc[nt][2] - mn1);
            s_acc[nt][3] = __expf(s_acc[nt][3] - mn1);
            ps0 += s_acc[nt][0] + s_acc[nt][1];
            ps1 += s_acc[nt][2] + s_acc[nt][3];
        }
        ps0 += __shfl_xor_sync(0xffffffffu, ps0, 1);
        ps0 += __shfl_xor_sync(0xffffffffu, ps0, 2);
        ps1 += __shfl_xor_sync(0xffffffffu, ps1, 1);
        ps1 += __shfl_xor_sync(0xffffffffu, ps1, 2);
        l_run[0] = l_run[0] * al0 + ps0;
        l_run[1] = l_run[1] * al1 + ps1;
#pragma unroll
        for (int nt = 0; nt < 16; nt++) {
            acc[nt][0] *= al0; acc[nt][1] *= al0;
            acc[nt][2] *= al1; acc[nt][3] *= al1;
        }

        uint32_t pa_h[4][4], pa_l[4][4];
#pragma unroll
        for (int s2 = 0; s2 < 4; s2++) {
            float* e = s_acc[2 * s2];
            float* o = s_acc[2 * s2 + 1];
            pa_h[s2][0] = pack_bf16x2(e[0], e[1]);
            pa_h[s2][1] = pack_bf16x2(e[2], e[3]);
            pa_h[s2][2] = pack_bf16x2(o[0], o[1]);
            pa_h[s2][3] = pack_bf16x2(o[2], o[3]);
#pragma unroll
            for (int q2 = 0; q2 < 4; q2++) {
                float r0 = (q2 < 2 ? e : o)[(q2 & 1) * 2];
                float r1 = (q2 < 2 ? e : o)[(q2 & 1) * 2 + 1];
                __nv_bfloat162* hh = (__nv_bfloat162*)&pa_h[s2][q2];
                pa_l[s2][q2] = pack_bf16x2(r0 - __bfloat162float(hh->x),
                                           r1 - __bfloat162float(hh->y));
            }
        }

#pragma unroll
        for (int s2 = 0; s2 < 4; s2++) {
            const int vrow = s2 * 16 + brow_b;
#pragma unroll
            for (int np = 0; np < 8; np++) {
                const uint32_t voff = vrow * 256 + (((np * 2 + (lane >> 4)) ^ (vrow & 7)) * 16);
                uint32_t vh[4], vl[4];
                LDSM4T(vh, sV  + voff);
                LDSM4T(vl, sVl + voff);
                MMA16816(acc[np * 2],     pa_h[s2], vh[0], vh[1]);
                MMA16816(acc[np * 2],     pa_h[s2], vl[0], vl[1]);
                MMA16816(acc[np * 2],     pa_l[s2], vh[0], vh[1]);
                MMA16816(acc[np * 2 + 1], pa_h[s2], vh[2], vh[3]);
                MMA16816(acc[np * 2 + 1], pa_h[s2], vl[2], vl[3]);
                MMA16816(acc[np * 2 + 1], pa_l[s2], vh[2], vh[3]);
            }
        }
    }

    const float il0 = 1.f / l_run[0];
    const float il1 = 1.f / l_run[1];
    const int row0 = t0 + wid * 16 + (lane >> 2);
#pragma unroll
    for (int nt = 0; nt < 16; nt++) {
        const int col = qh * HDIM + nt * 8 + (lane & 3) * 2;
        float o0 = acc[nt][0] * il0, o1 = acc[nt][1] * il0;
        float o2 = acc[nt][2] * il1, o3 = acc[nt][3] * il1;
        uint32_t h01 = pack_bf16x2(o0, o1);
        uint32_t h23 = pack_bf16x2(o2, o3);
        __nv_bfloat162* p01 = (__nv_bfloat162*)&h01;
        __nv_bfloat162* p23 = (__nv_bfloat162*)&h23;
        uint32_t l01 = pack_bf16x2(o0 - __bfloat162float(p01->x), o1 - __bfloat162float(p01->y));
        uint32_t l23 = pack_bf16x2(o2 - __bfloat162float(p23->x), o3 - __bfloat162float(p23->y));
        *(uint32_t*)(g_att_hi + (size_t)row0 * NQK + col)       = h01;
        *(uint32_t*)(g_att_lo + (size_t)row0 * NQK + col)       = l01;
        *(uint32_t*)(g_att_hi + (size_t)(row0 + 8) * NQK + col) = h23;
        *(uint32_t*)(g_att_lo + (size_t)(row0 + 8) * NQK + col) = l23;
    }
}

// ---------------- launch ----------------
extern "C" void kernel_launch(void* const* d_in, const int* in_sizes, int n_in,
                              void* d_out, int out_size)
{
    const float* hidden    = (const float*)d_in[0];
    const int*   positions = (const int*)  d_in[1];
    const float* wq        = (const float*)d_in[2];
    const float* bq        = (const float*)d_in[3];
    const float* wk        = (const float*)d_in[4];
    const float* bk        = (const float*)d_in[5];
    const float* wv        = (const float*)d_in[6];
    const float* bv        = (const float*)d_in[7];
    const float* wo        = (const float*)d_in[8];
    (void)in_sizes; (void)n_in; (void)out_size;

    float* out    = (float*)d_out;                 // [T, HID]
    float* out_kv = out + (size_t)TOK * HID;       // [T, 8, 128]

    float* qkv;
    cudaGetSymbolAddress((void**)&qkv, g_qkv);
    __nv_bfloat16 *hid_hi, *hid_lo, *wqkvt_hi, *wqkvt_lo, *wot_hi, *wot_lo, *att_hi, *att_lo;
    cudaGetSymbolAddress((void**)&hid_hi,   g_hid_hi);
    cudaGetSymbolAddress((void**)&hid_lo,   g_hid_lo);
    cudaGetSymbolAddress((void**)&wqkvt_hi, g_wqkvt_hi);
    cudaGetSymbolAddress((void**)&wqkvt_lo, g_wqkvt_lo);
    cudaGetSymbolAddress((void**)&wot_hi,   g_wot_hi);
    cudaGetSymbolAddress((void**)&wot_lo,   g_wot_lo);
    cudaGetSymbolAddress((void**)&att_hi,   g_att_hi);
    cudaGetSymbolAddress((void**)&att_lo,   g_att_lo);

    cudaFuncSetAttribute(gemm_hmma256<0>, cudaFuncAttributeMaxDynamicSharedMemorySize, G2_SMEM);
    cudaFuncSetAttribute(gemm_hmma256<1>, cudaFuncAttributeMaxDynamicSharedMemorySize, G2_SMEM);
    cudaFuncSetAttribute(gemm_hmma128,    cudaFuncAttributeMaxDynamicSharedMemorySize, G1_SMEM);
    cudaFuncSetAttribute(attn_hmma, cudaFuncAttributeMaxDynamicSharedMemorySize, A_SMEM);

    // conversions
    split_convert<<<(TOK * HID / 4 + 255) / 256, 256>>>(hidden, hid_hi, hid_lo, TOK * HID);
    split_transpose<<<dim3(NQK / 32,  HID / 32), 256>>>(wq, wqkvt_hi, wqkvt_lo, HID, NQK);
    split_transpose<<<dim3(NKVD / 32, HID / 32), 256>>>(
        wk, wqkvt_hi + (size_t)NQK * HID, wqkvt_lo + (size_t)NQK * HID, HID, NKVD);
    split_transpose<<<dim3(NKVD / 32, HID / 32), 256>>>(
        wv, wqkvt_hi + (size_t)(NQK + NKVD) * HID, wqkvt_lo + (size_t)(NQK + NKVD) * HID, HID, NKVD);
    split_transpose<<<dim3(HID / 32, NQK / 32), 256>>>(wo, wot_hi, wot_lo, NQK, HID);

    // fused QKV projection (+concat bias in epilogue), 128x256 tiles
    gemm_hmma256<1><<<dim3(NQKV / 256, TOK / 128), 256, G2_SMEM>>>(
        hid_hi, hid_lo, wqkvt_hi, wqkvt_lo, bq, bk, bv, qkv, NQKV, HID);

    // RoPE + kv_fused output + bf16 splits
    rope_scatter<<<(TOK * 64 + 255) / 256, 256>>>(positions, out_kv);

    // HMMA flash attention (double-buffered KV)
    attn_hmma<<<dim3(NQH, SEQL / 128, 4), 256, A_SMEM>>>();

    // o_proj: 128x128 tiles, 2 CTAs/SM (finer wave granularity)
    gemm_hmma128<<<dim3(HID / 128, TOK / 128), 128, G1_SMEM>>>(
        att_hi, att_lo, wot_hi, wot_lo, out, HID, NQK);
}

// round 14
// speedup vs baseline: 1.5903x; 1.5495x over previous
#include <cuda_runtime.h>
#include <cuda_bf16.h>
#include <math.h>
#include <stdint.h>

#define TOK    4096
#define HID    3584
#define NQH    28
#define NKVH   4
#define HDIM   128
#define SEQL   1024
#define GQA    7
#define QSCALE 0.08838834764831845f   // 1/sqrt(128)
#define NQK    (NQH * HDIM)           // 3584
#define NKVD   (NKVH * HDIM)          // 512
#define NQKV   (NQK + 2 * NKVD)       // 4608

// ---------------- scratch (device globals) ----------------
__device__ float g_qkv[(size_t)TOK * NQKV];     // fused QKV projection output (fp32)

__device__ __nv_bfloat16 g_hid_hi[(size_t)TOK * HID];
__device__ __nv_bfloat16 g_hid_lo[(size_t)TOK * HID];
__device__ __nv_bfloat16 g_wqkvt_hi[(size_t)NQKV * HID];
__device__ __nv_bfloat16 g_wqkvt_lo[(size_t)NQKV * HID];
__device__ __nv_bfloat16 g_wot_hi[(size_t)HID * NQK];
__device__ __nv_bfloat16 g_wot_lo[(size_t)HID * NQK];

__device__ __nv_bfloat16 g_q_hi[(size_t)TOK * NQK];   // roped+scaled Q
__device__ __nv_bfloat16 g_q_lo[(size_t)TOK * NQK];
__device__ __nv_bfloat16 g_k_hi[(size_t)TOK * NKVD];  // roped K
__device__ __nv_bfloat16 g_k_lo[(size_t)TOK * NKVD];
__device__ __nv_bfloat16 g_v_hi[(size_t)TOK * NKVD];
__device__ __nv_bfloat16 g_v_lo[(size_t)TOK * NKVD];
__device__ __nv_bfloat16 g_att_hi[(size_t)TOK * NQK]; // attention out
__device__ __nv_bfloat16 g_att_lo[(size_t)TOK * NQK];

// ==================== PTX helpers ====================
__device__ __forceinline__ uint32_t smem_to_u32(const void* p) {
    uint32_t a;
    asm("{ .reg .u64 t; cvta.to.shared.u64 t, %1; cvt.u32.u64 %0, t; }" : "=r"(a) : "l"(p));
    return a;
}
#define CP_ASYNC16(dst, src) \
    asm volatile("cp.async.cg.shared.global [%0], [%1], 16;" :: "r"(dst), "l"(src))
#define CP_COMMIT() asm volatile("cp.async.commit_group;" ::: "memory")
#define CP_WAIT1()  asm volatile("cp.async.wait_group 1;" ::: "memory")

#define LDSM4(r, addr) \
    asm volatile("ldmatrix.sync.aligned.m8n8.x4.shared.b16 {%0,%1,%2,%3}, [%4];" \
        : "=r"((r)[0]), "=r"((r)[1]), "=r"((r)[2]), "=r"((r)[3]) : "r"(addr))
#define LDSM4T(r, addr) \
    asm volatile("ldmatrix.sync.aligned.m8n8.x4.trans.shared.b16 {%0,%1,%2,%3}, [%4];" \
        : "=r"((r)[0]), "=r"((r)[1]), "=r"((r)[2]), "=r"((r)[3]) : "r"(addr))

#define MMA16816(d, a, b0, b1) \
    asm volatile("mma.sync.aligned.m16n8k16.row.col.f32.bf16.bf16.f32 " \
        "{%0,%1,%2,%3}, {%4,%5,%6,%7}, {%8,%9}, {%0,%1,%2,%3};" \
        : "+f"((d)[0]), "+f"((d)[1]), "+f"((d)[2]), "+f"((d)[3]) \
        : "r"((a)[0]), "r"((a)[1]), "r"((a)[2]), "r"((a)[3]), "r"(b0), "r"(b1))

__device__ __forceinline__ uint32_t pack_bf16x2(float a, float b) {
    __nv_bfloat162 h = __floats2bfloat162_rn(a, b);
    return *(uint32_t*)&h;
}

// ==================== split/convert kernels ====================
__global__ void split_convert(const float* __restrict__ src,
                              __nv_bfloat16* __restrict__ hi,
                              __nv_bfloat16* __restrict__ lo, int n)
{
    int i = (blockIdx.x * blockDim.x + threadIdx.x) * 4;
    if (i >= n) return;
    float4 v = *(const float4*)(src + i);
    __nv_bfloat16 h0 = __float2bfloat16(v.x), h1 = __float2bfloat16(v.y);
    __nv_bfloat16 h2 = __float2bfloat16(v.z), h3 = __float2bfloat16(v.w);
    __nv_bfloat16 l0 = __float2bfloat16(v.x - __bfloat162float(h0));
    __nv_bfloat16 l1 = __float2bfloat16(v.y - __bfloat162float(h1));
    __nv_bfloat16 l2 = __float2bfloat16(v.z - __bfloat162float(h2));
    __nv_bfloat16 l3 = __float2bfloat16(v.w - __bfloat162float(h3));
    *(__nv_bfloat162*)(hi + i)     = __nv_bfloat162(h0, h1);
    *(__nv_bfloat162*)(hi + i + 2) = __nv_bfloat162(h2, h3);
    *(__nv_bfloat162*)(lo + i)     = __nv_bfloat162(l0, l1);
    *(__nv_bfloat162*)(lo + i + 2) = __nv_bfloat162(l2, l3);
}

// src [R, C] fp32 -> dst [C, R] bf16 hi/lo
__global__ void split_transpose(const float* __restrict__ src,
                                __nv_bfloat16* __restrict__ hi,
                                __nv_bfloat16* __restrict__ lo, int R, int C)
{
    __shared__ float t[32][33];
    const int tx = threadIdx.x & 31;
    const int ty = threadIdx.x >> 5;
    const int r0 = blockIdx.y * 32;
    const int c0 = blockIdx.x * 32;
#pragma unroll
    for (int i = 0; i < 4; i++) {
        int r = ty + 8 * i;
        t[r][tx] = src[(size_t)(r0 + r) * C + c0 + tx];
    }
    __syncthreads();
#pragma unroll
    for (int i = 0; i < 4; i++) {
        int r = ty + 8 * i;
        float x = t[tx][r];
        __nv_bfloat16 h = __float2bfloat16(x);
        __nv_bfloat16 l = __float2bfloat16(x - __bfloat162float(h));
        size_t o = (size_t)(c0 + r) * R + r0 + tx;
        hi[o] = h;
        lo[o] = l;
    }
}

// ==================== HMMA bf16x3 GEMM, 128x256 tile, 3-stage ====================
// C[M,N] = A[M,K]*B[N,K]^T (+bias). 8 warps (2M x 4N), warp tile 64x64.
#define G2_AHI 0
#define G2_ALO 8192
#define G2_BHI 16384
#define G2_BLO 32768
#define G2_STAGE 49152
#define G2_SMEM (3 * G2_STAGE)

// BMODE: 0 = no bias, 1 = concat bias (b0: NQK, b1: NKVD, b2: NKVD)
template <int BMODE>
__global__ __launch_bounds__(256, 1) void gemm_hmma256(
    const __nv_bfloat16* __restrict__ Ahi, const __nv_bfloat16* __restrict__ Alo,
    const __nv_bfloat16* __restrict__ Bhi, const __nv_bfloat16* __restrict__ Blo,
    const float* __restrict__ b0, const float* __restrict__ b1,
    const float* __restrict__ b2, float* __restrict__ C, int N, int K)
{
    extern __shared__ char smem[];
    const uint32_t sb = smem_to_u32(smem);
    const int tid  = threadIdx.x;
    const int wid  = tid >> 5;
    const int lane = tid & 31;
    const int bn   = blockIdx.x * 256;
    const int bm   = blockIdx.y * 128;
    const int m0   = (wid >> 2) * 64;
    const int n0   = (wid & 3) * 64;

    float acc[4][8][4];
#pragma unroll
    for (int i = 0; i < 4; i++)
#pragma unroll
        for (int j = 0; j < 8; j++)
#pragma unroll
            for (int r = 0; r < 4; r++) acc[i][j][r] = 0.f;

    auto load_stage = [&](int ks, int buf) {
        const uint32_t sbase = sb + buf * G2_STAGE;
#pragma unroll
        for (int u = 0; u < 12; u++) {
            const int s = u * 256 + tid;
            const __nv_bfloat16* src;
            uint32_t dbase;
            int r, ch;
            if (s < 1024) {
                const int bsel = s >> 9, idx = s & 511;
                r = idx >> 2; ch = idx & 3;
                src = (bsel ? Alo : Ahi) + (size_t)(bm + r) * K;
                dbase = bsel ? G2_ALO : G2_AHI;
            } else {
                const int t2 = s - 1024;
                const int bsel = t2 >> 10, idx = t2 & 1023;
                r = idx >> 2; ch = idx & 3;
                src = (bsel ? Blo : Bhi) + (size_t)(bn + r) * K;
                dbase = bsel ? G2_BLO : G2_BHI;
            }
            const int chs = ch ^ ((r ^ (r >> 2)) & 3);
            CP_ASYNC16(sbase + dbase + r * 64 + chs * 16, src + ks * 32 + ch * 8);
        }
    };

    auto compute = [&](int buf) {
        const uint32_t st = sb + buf * G2_STAGE;
#pragma unroll
        for (int ks = 0; ks < 2; ks++) {
            uint32_t ah[4][4], al[4][4];
#pragma unroll
            for (int i = 0; i < 4; i++) {
                const int row = m0 + i * 16 + (lane & 15);
                const int ch  = (ks * 2 + (lane >> 4)) ^ ((row ^ (row >> 2)) & 3);
                LDSM4(ah[i], st + G2_AHI + row * 64 + ch * 16);
                LDSM4(al[i], st + G2_ALO + row * 64 + ch * 16);
            }
#pragma unroll
            for (int nb = 0; nb < 4; nb++) {
                const int row = n0 + nb * 16 + ((lane >> 3) & 1) * 8 + (lane & 7);
                const int ch  = (ks * 2 + (lane >> 4)) ^ ((row ^ (row >> 2)) & 3);
                uint32_t bh[4], bl[4];
                LDSM4(bh, st + G2_BHI + row * 64 + ch * 16);
                LDSM4(bl, st + G2_BLO + row * 64 + ch * 16);
#pragma unroll
                for (int i = 0; i < 4; i++) {
                    MMA16816(acc[i][nb * 2],     ah[i], bh[0], bh[2]);
                    MMA16816(acc[i][nb * 2],     ah[i], bl[0], bl[2]);
                    MMA16816(acc[i][nb * 2],     al[i], bh[0], bh[2]);
                    MMA16816(acc[i][nb * 2 + 1], ah[i], bh[1], bh[3]);
                    MMA16816(acc[i][nb * 2 + 1], ah[i], bl[1], bl[3]);
                    MMA16816(acc[i][nb * 2 + 1], al[i], bh[1], bh[3]);
                }
            }
        }
    };

    const int nst = K >> 5;
    load_stage(0, 0); CP_COMMIT();
    load_stage(1, 1); CP_COMMIT();
    int buf = 0;
    for (int s = 0; s < nst; s++) {
        CP_WAIT1();
        __syncthreads();
        const int np = s + 2;
        if (np < nst) load_stage(np, (buf + 2) % 3);
        CP_COMMIT();
        compute(buf);
        buf = (buf + 1) % 3;
    }

    auto bias_at = [&](int col) -> float {
        if (BMODE == 0) return 0.f;
        if (col < NQK) return b0[col];
        if (col < NQK + NKVD) return b1[col - NQK];
        return b2[col - NQK - NKVD];
    };
#pragma unroll
    for (int i = 0; i < 4; i++) {
        const int row = bm + m0 + i * 16 + (lane >> 2);
#pragma unroll
        for (int j = 0; j < 8; j++) {
            const int col = bn + n0 + j * 8 + (lane & 3) * 2;
            const float c0 = bias_at(col), c1 = bias_at(col + 1);
            float2 v;
            v.x = acc[i][j][0] + c0; v.y = acc[i][j][1] + c1;
            *(float2*)(C + (size_t)row * N + col) = v;
            v.x = acc[i][j][2] + c0; v.y = acc[i][j][3] + c1;
            *(float2*)(C + (size_t)(row + 8) * N + col) = v;
        }
    }
}

// ==================== HMMA bf16x3 GEMM, 128x128 tile, 2 CTAs/SM ====================
#define G1_AHI 0
#define G1_ALO 8192
#define G1_BHI 16384
#define G1_BLO 24576
#define G1_STAGE 32768
#define G1_SMEM (3 * G1_STAGE)

__global__ __launch_bounds__(128, 2) void gemm_hmma128(
    const __nv_bfloat16* __restrict__ Ahi, const __nv_bfloat16* __restrict__ Alo,
    const __nv_bfloat16* __restrict__ Bhi, const __nv_bfloat16* __restrict__ Blo,
    float* __restrict__ C, int N, int K)
{
    extern __shared__ char smem[];
    const uint32_t sb = smem_to_u32(smem);
    const int tid  = threadIdx.x;
    const int wid  = tid >> 5;
    const int lane = tid & 31;
    const int bn   = blockIdx.x * 128;
    const int bm   = blockIdx.y * 128;
    const int m0   = (wid >> 1) * 64;
    const int n0   = (wid & 1) * 64;

    float acc[4][8][4];
#pragma unroll
    for (int i = 0; i < 4; i++)
#pragma unroll
        for (int j = 0; j < 8; j++)
#pragma unroll
            for (int r = 0; r < 4; r++) acc[i][j][r] = 0.f;

    auto load_stage = [&](int ks, int buf) {
        const uint32_t sbase = sb + buf * G1_STAGE;
#pragma unroll
        for (int u = 0; u < 16; u++) {
            const int s     = u * 128 + tid;
            const int which = s >> 9;            // 0:Ahi 1:Alo 2:Bhi 3:Blo
            const int idx   = s & 511;
            const int r     = idx >> 2;
            const int ch    = idx & 3;
            const __nv_bfloat16* src;
            if (which == 0)      src = Ahi + (size_t)(bm + r) * K;
            else if (which == 1) src = Alo + (size_t)(bm + r) * K;
            else if (which == 2) src = Bhi + (size_t)(bn + r) * K;
            else                 src = Blo + (size_t)(bn + r) * K;
            const int chs = ch ^ ((r ^ (r >> 2)) & 3);
            CP_ASYNC16(sbase + which * 8192 + r * 64 + chs * 16, src + ks * 32 + ch * 8);
        }
    };

    auto compute = [&](int buf) {
        const uint32_t st = sb + buf * G1_STAGE;
#pragma unroll
        for (int ks = 0; ks < 2; ks++) {
            uint32_t ah[4][4], al[4][4];
#pragma unroll
            for (int i = 0; i < 4; i++) {
                const int row = m0 + i * 16 + (lane & 15);
                const int ch  = (ks * 2 + (lane >> 4)) ^ ((row ^ (row >> 2)) & 3);
                LDSM4(ah[i], st + G1_AHI + row * 64 + ch * 16);
                LDSM4(al[i], st + G1_ALO + row * 64 + ch * 16);
            }
#pragma unroll
            for (int nb = 0; nb < 4; nb++) {
                const int row = n0 + nb * 16 + ((lane >> 3) & 1) * 8 + (lane & 7);
                const int ch  = (ks * 2 + (lane >> 4)) ^ ((row ^ (row >> 2)) & 3);
                uint32_t bh[4], bl[4];
                LDSM4(bh, st + G1_BHI + row * 64 + ch * 16);
                LDSM4(bl, st + G1_BLO + row * 64 + ch * 16);
#pragma unroll
                for (int i = 0; i < 4; i++) {
                    MMA16816(acc[i][nb * 2],     ah[i], bh[0], bh[2]);
                    MMA16816(acc[i][nb * 2],     ah[i], bl[0], bl[2]);
                    MMA16816(acc[i][nb * 2],     al[i], bh[0], bh[2]);
                    MMA16816(acc[i][nb * 2 + 1], ah[i], bh[1], bh[3]);
                    MMA16816(acc[i][nb * 2 + 1], ah[i], bl[1], bl[3]);
                    MMA16816(acc[i][nb * 2 + 1], al[i], bh[1], bh[3]);
                }
            }
        }
    };

    const int nst = K >> 5;
    load_stage(0, 0); CP_COMMIT();
    load_stage(1, 1); CP_COMMIT();
    int buf = 0;
    for (int s = 0; s < nst; s++) {
        CP_WAIT1();
        __syncthreads();
        const int np = s + 2;
        if (np < nst) load_stage(np, (buf + 2) % 3);
        CP_COMMIT();
        compute(buf);
        buf = (buf + 1) % 3;
    }

#pragma unroll
    for (int i = 0; i < 4; i++) {
        const int row = bm + m0 + i * 16 + (lane >> 2);
#pragma unroll
        for (int j = 0; j < 8; j++) {
            const int col = bn + n0 + j * 8 + (lane & 3) * 2;
            float2 v;
            v.x = acc[i][j][0]; v.y = acc[i][j][1];
            *(float2*)(C + (size_t)row * N + col) = v;
            v.x = acc[i][j][2]; v.y = acc[i][j][3];
            *(float2*)(C + (size_t)(row + 8) * N + col) = v;
        }
    }
}

// ---------------- RoPE + kv_fused scatter + bf16 split ----------------
__global__ void rope_scatter(const int* __restrict__ positions,
                             float* __restrict__ kv_out)
{
    const int idx = blockIdx.x * blockDim.x + threadIdx.x;
    if (idx >= TOK * 64) return;
    const int d = idx & 63;
    const int t = idx >> 6;
    const int pos = positions[t];
    const float inv = exp2f((float)d * -0.31143075693324f);  // theta^(-d/64)
    float sv, cv;
    sincosf((float)pos * inv, &sv, &cv);

    const float* row = g_qkv + (size_t)t * NQKV;

    const size_t qb = (size_t)t * NQK;
#pragma unroll 4
    for (int h = 0; h < NQH; h++) {
        const float x1 = row[h * HDIM + d], x2 = row[h * HDIM + d + 64];
        const float y1 = (x1 * cv - x2 * sv) * QSCALE;
        const float y2 = (x2 * cv + x1 * sv) * QSCALE;
        const __nv_bfloat16 h1 = __float2bfloat16(y1), h2 = __float2bfloat16(y2);
        g_q_hi[qb + h * HDIM + d]      = h1;
        g_q_lo[qb + h * HDIM + d]      = __float2bfloat16(y1 - __bfloat162float(h1));
        g_q_hi[qb + h * HDIM + d + 64] = h2;
        g_q_lo[qb + h * HDIM + d + 64] = __float2bfloat16(y2 - __bfloat162float(h2));
    }

    const size_t kb = (size_t)t * NKVD;
#pragma unroll
    for (int kh = 0; kh < NKVH; kh++) {
        const float x1 = row[NQK + kh * HDIM + d], x2 = row[NQK + kh * HDIM + d + 64];
        const float y1 = x1 * cv - x2 * sv;
        const float y2 = x2 * cv + x1 * sv;
        float* dst = kv_out + ((size_t)t * 8 + kh) * HDIM;
        dst[d] = y1; dst[d + 64] = y2;
        const __nv_bfloat16 h1 = __float2bfloat16(y1), h2 = __float2bfloat16(y2);
        g_k_hi[kb + kh * HDIM + d]      = h1;
        g_k_lo[kb + kh * HDIM + d]      = __float2bfloat16(y1 - __bfloat162float(h1));
        g_k_hi[kb + kh * HDIM + d + 64] = h2;
        g_k_lo[kb + kh * HDIM + d + 64] = __float2bfloat16(y2 - __bfloat162float(h2));
    }
#pragma unroll
    for (int vh = 0; vh < NKVH; vh++) {
        const float x1 = row[NQK + NKVD + vh * HDIM + d];
        const float x2 = row[NQK + NKVD + vh * HDIM + d + 64];
        float* dst = kv_out + ((size_t)t * 8 + 4 + vh) * HDIM;
        dst[d] = x1; dst[d + 64] = x2;
        const __nv_bfloat16 h1 = __float2bfloat16(x1), h2 = __float2bfloat16(x2);
        g_v_hi[kb + vh * HDIM + d]      = h1;
        g_v_lo[kb + vh * HDIM + d]      = __float2bfloat16(x1 - __bfloat162float(h1));
        g_v_hi[kb + vh * HDIM + d + 64] = h2;
        g_v_lo[kb + vh * HDIM + d + 64] = __float2bfloat16(x2 - __bfloat162float(h2));
    }
}

// ==================== HMMA flash attention (double-buffered KV) ====================
#define A_QHI 0
#define A_QLO 32768
#define A_KV  65536
#define A_KVSTAGE 65536
#define A_SMEM (A_KV + 2 * A_KVSTAGE)

__global__ __launch_bounds__(256, 1) void attn_hmma()
{
    extern __shared__ char smem[];
    const uint32_t sb = smem_to_u32(smem);
    const int tid  = threadIdx.x;
    const int wid  = tid >> 5;
    const int lane = tid & 31;
    const int qh   = blockIdx.x;
    const int qt   = (gridDim.y - 1) - blockIdx.y;  // heavy tiles first
    const int b    = blockIdx.z;
    const int kvh  = qh / GQA;
    const int t0   = b * SEQL + qt * 128;

#pragma unroll
    for (int u = 0; u < 16; u++) {
        const int s   = u * 256 + tid;
        const int bsel = s >> 11;
        const int r   = (s >> 4) & 127;
        const int ch  = s & 15;
        const __nv_bfloat16* src =
            (bsel ? g_q_lo : g_q_hi) + (size_t)(t0 + r) * NQK + qh * HDIM + ch * 8;
        CP_ASYNC16(sb + (bsel ? A_QLO : A_QHI) + r * 256 + ((ch ^ (r & 7)) * 16), src);
    }
    CP_COMMIT();

    const int ktmax = 2 * qt + 2;

    auto load_kv = [&](int kt, int buf) {
        const int tk = b * SEQL + kt * 64;
        const uint32_t stb = sb + A_KV + buf * A_KVSTAGE;
#pragma unroll
        for (int u = 0; u < 16; u++) {
            const int s    = u * 256 + tid;
            const int bsel = s >> 10;           // 0:Khi 1:Klo 2:Vhi 3:Vlo
            const int r    = (s >> 4) & 63;
            const int ch   = s & 15;
            const __nv_bfloat16* base =
                (bsel == 0) ? g_k_hi : (bsel == 1) ? g_k_lo : (bsel == 2) ? g_v_hi : g_v_lo;
            const __nv_bfloat16* src = base + (size_t)(tk + r) * NKVD + kvh * HDIM + ch * 8;
            CP_ASYNC16(stb + bsel * 16384 + r * 256 + ((ch ^ (r & 7)) * 16), src);
        }
    };

    load_kv(0, 0);
    CP_COMMIT();

    float m_run[2] = {-1e30f, -1e30f};
    float l_run[2] = {0.f, 0.f};
    float acc[16][4];
#pragma unroll
    for (int nt = 0; nt < 16; nt++)
#pragma unroll
        for (int r = 0; r < 4; r++) acc[nt][r] = 0.f;

    const int arow   = wid * 16 + (lane & 15);
    const int brow_b = ((lane >> 3) & 1) * 8 + (lane & 7);

    for (int kt = 0; kt < ktmax; kt++) {
        __syncthreads();
        if (kt + 1 < ktmax) load_kv(kt + 1, (kt + 1) & 1);
        CP_COMMIT();
        CP_WAIT1();
        __syncthreads();

        // masked-warp skip: this warp's rows [qt*128+wid*16, +16) are ALL below
        // the tile's column range -> every score is masked -> tile is an exact
        // no-op (alpha=1, psum=0). Loads/barriers already done; skip compute.
        if (kt * 64 > qt * 128 + wid * 16 + 15) continue;

        const uint32_t stq = sb + A_KV + (kt & 1) * A_KVSTAGE;
        const uint32_t sK  = stq;
        const uint32_t sKl = stq + 16384;
        const uint32_t sV  = stq + 32768;
        const uint32_t sVl = stq + 49152;

        float s_acc[8][4];
#pragma unroll
        for (int nt = 0; nt < 8; nt++)
#pragma unroll
            for (int r = 0; r < 4; r++) s_acc[nt][r] = 0.f;

#pragma unroll
        for (int ks = 0; ks < 8; ks++) {
            uint32_t ah[4], al[4];
            const uint32_t aoff = arow * 256 + (((ks * 2 + (lane >> 4)) ^ (arow & 7)) * 16);
            LDSM4(ah, sb + A_QHI + aoff);
            LDSM4(al, sb + A_QLO + aoff);
#pragma unroll
            for (int nb = 0; nb < 4; nb++) {
                const int brow = nb * 16 + brow_b;
                const uint32_t boff = brow * 256 + (((ks * 2 + (lane >> 4)) ^ (brow & 7)) * 16);
                uint32_t bh[4], bl[4];
                LDSM4(bh, sK  + boff);
                LDSM4(bl, sKl + boff);
                MMA16816(s_acc[nb * 2],     ah, bh[0], bh[2]);
                MMA16816(s_acc[nb * 2],     ah, bl[0], bl[2]);
                MMA16816(s_acc[nb * 2],     al, bh[0], bh[2]);
                MMA16816(s_acc[nb * 2 + 1], ah, bh[1], bh[3]);
                MMA16816(s_acc[nb * 2 + 1], ah, bl[1], bl[3]);
                MMA16816(s_acc[nb * 2 + 1], al, bh[1], bh[3]);
            }
        }

        if (kt >= 2 * qt) {
            const int row0 = qt * 128 + wid * 16 + (lane >> 2);
            const int colb = kt * 64 + (lane & 3) * 2;
#pragma unroll
            for (int nt = 0; nt < 8; nt++) {
                const int c0 = colb + nt * 8;
                if (c0     > row0)     s_acc[nt][0] = -1e30f;
                if (c0 + 1 > row0)     s_acc[nt][1] = -1e30f;
                if (c0     > row0 + 8) s_acc[nt][2] = -1e30f;
                if (c0 + 1 > row0 + 8) s_acc[nt][3] = -1e30f;
            }
        }

        float ml0 = -1e30f, ml1 = -1e30f;
#pragma unroll
        for (int nt = 0; nt < 8; nt++) {
            ml0 = fmaxf(ml0, fmaxf(s_acc[nt][0], s_acc[nt][1]));
            ml1 = fmaxf(ml1, fmaxf(s_acc[nt][2], s_acc[nt][3]));
        }
        ml0 = fmaxf(ml0, __shfl_xor_sync(0xffffffffu, ml0, 1));
        ml0 = fmaxf(ml0, __shfl_xor_sync(0xffffffffu, ml0, 2));
        ml1 = fmaxf(ml1, __shfl_xor_sync(0xffffffffu, ml1, 1));
        ml1 = fmaxf(ml1, __shfl_xor_sync(0xffffffffu, ml1, 2));
        const float mn0 = fmaxf(m_run[0], ml0);
        const float mn1 = fmaxf(m_run[1], ml1);
        const float al0 = __expf(m_run[0] - mn0);
        const float al1 = __expf(m_run[1] - mn1);
        m_run[0] = mn0; m_run[1] = mn1;

        float ps0 = 0.f, ps1 = 0.f;
#pragma unroll
        for (int nt = 0; nt < 8; nt++) {
            s_acc[nt][0] = __expf(s_acc[nt][0] - mn0);
            s_acc[nt][1] = __expf(s_acc[nt][1] - mn0);
            s_acc[nt][2] = __expf(s_acc[nt][2] - mn1);
            s_acc[nt][3] = __expf(s_acc[nt][3] - mn1);
            ps0 += s_acc[nt][0] + s_acc[nt][1];
            ps1 += s_acc[nt][2] + s_acc[nt][3];
        }
        ps0 += __shfl_xor_sync(0xffffffffu, ps0, 1);
        ps0 += __shfl_xor_sync(0xffffffffu, ps0, 2);
        ps1 += __shfl_xor_sync(0xffffffffu, ps1, 1);
        ps1 += __shfl_xor_sync(0xffffffffu, ps1, 2);
        l_run[0] = l_run[0] * al0 + ps0;
        l_run[1] = l_run[1] * al1 + ps1;
#pragma unroll
        for (int nt = 0; nt < 16; nt++) {
            acc[nt][0] *= al0; acc[nt][1] *= al0;
            acc[nt][2] *= al1; acc[nt][3] *= al1;
        }

        uint32_t pa_h[4][4], pa_l[4][4];
#pragma unroll
        for (int s2 = 0; s2 < 4; s2++) {
            float* e = s_acc[2 * s2];
            float* o = s_acc[2 * s2 + 1];
            pa_h[s2][0] = pack_bf16x2(e[0], e[1]);
            pa_h[s2][1] = pack_bf16x2(e[2], e[3]);
            pa_h[s2][2] = pack_bf16x2(o[0], o[1]);
            pa_h[s2][3] = pack_bf16x2(o[2], o[3]);
#pragma unroll
            for (int q2 = 0; q2 < 4; q2++) {
                float r0 = (q2 < 2 ? e : o)[(q2 & 1) * 2];
                float r1 = (q2 < 2 ? e : o)[(q2 & 1) * 2 + 1];
                __nv_bfloat162* hh = (__nv_bfloat162*)&pa_h[s2][q2];
                pa_l[s2][q2] = pack_bf16x2(r0 - __bfloat162float(hh->x),
                                           r1 - __bfloat162float(hh->y));
            }
        }

#pragma unroll
        for (int s2 = 0; s2 < 4; s2++) {
            const int vrow = s2 * 16 + brow_b;
#pragma unroll
            for (int np = 0; np < 8; np++) {
                const uint32_t voff = vrow * 256 + (((np * 2 + (lane >> 4)) ^ (vrow & 7)) * 16);
                uint32_t vh[4], vl[4];
                LDSM4T(vh, sV  + voff);
                LDSM4T(vl, sVl + voff);
                MMA16816(acc[np * 2],     pa_h[s2], vh[0], vh[1]);
                MMA16816(acc[np * 2],     pa_h[s2], vl[0], vl[1]);
                MMA16816(acc[np * 2],     pa_l[s2], vh[0], vh[1]);
                MMA16816(acc[np * 2 + 1], pa_h[s2], vh[2], vh[3]);
                MMA16816(acc[np * 2 + 1], pa_h[s2], vl[2], vl[3]);
                MMA16816(acc[np * 2 + 1], pa_l[s2], vh[2], vh[3]);
            }
        }
    }

    const float il0 = 1.f / l_run[0];
    const float il1 = 1.f / l_run[1];
    const int row0 = t0 + wid * 16 + (lane >> 2);
#pragma unroll
    for (int nt = 0; nt < 16; nt++) {
        const int col = qh * HDIM + nt * 8 + (lane & 3) * 2;
        float o0 = acc[nt][0] * il0, o1 = acc[nt][1] * il0;
        float o2 = acc[nt][2] * il1, o3 = acc[nt][3] * il1;
        uint32_t h01 = pack_bf16x2(o0, o1);
        uint32_t h23 = pack_bf16x2(o2, o3);
        __nv_bfloat162* p01 = (__nv_bfloat162*)&h01;
        __nv_bfloat162* p23 = (__nv_bfloat162*)&h23;
        uint32_t l01 = pack_bf16x2(o0 - __bfloat162float(p01->x), o1 - __bfloat162float(p01->y));
        uint32_t l23 = pack_bf16x2(o2 - __bfloat162float(p23->x), o3 - __bfloat162float(p23->y));
        *(uint32_t*)(g_att_hi + (size_t)row0 * NQK + col)       = h01;
        *(uint32_t*)(g_att_lo + (size_t)row0 * NQK + col)       = l01;
        *(uint32_t*)(g_att_hi + (size_t)(row0 + 8) * NQK + col) = h23;
        *(uint32_t*)(g_att_lo + (size_t)(row0 + 8) * NQK + col) = l23;
    }
}

// ---------------- launch ----------------
extern "C" void kernel_launch(void* const* d_in, const int* in_sizes, int n_in,
                              void* d_out, int out_size)
{
    const float* hidden    = (const float*)d_in[0];
    const int*   positions = (const int*)  d_in[1];
    const float* wq        = (const float*)d_in[2];
    const float* bq        = (const float*)d_in[3];
    const float* wk        = (const float*)d_in[4];
    const float* bk        = (const float*)d_in[5];
    const float* wv        = (const float*)d_in[6];
    const float* bv        = (const float*)d_in[7];
    const float* wo        = (const float*)d_in[8];
    (void)in_sizes; (void)n_in; (void)out_size;

    float* out    = (float*)d_out;                 // [T, HID]
    float* out_kv = out + (size_t)TOK * HID;       // [T, 8, 128]

    float* qkv;
    cudaGetSymbolAddress((void**)&qkv, g_qkv);
    __nv_bfloat16 *hid_hi, *hid_lo, *wqkvt_hi, *wqkvt_lo, *wot_hi, *wot_lo, *att_hi, *att_lo;
    cudaGetSymbolAddress((void**)&hid_hi,   g_hid_hi);
    cudaGetSymbolAddress((void**)&hid_lo,   g_hid_lo);
    cudaGetSymbolAddress((void**)&wqkvt_hi, g_wqkvt_hi);
    cudaGetSymbolAddress((void**)&wqkvt_lo, g_wqkvt_lo);
    cudaGetSymbolAddress((void**)&wot_hi,   g_wot_hi);
    cudaGetSymbolAddress((void**)&wot_lo,   g_wot_lo);
    cudaGetSymbolAddress((void**)&att_hi,   g_att_hi);
    cudaGetSymbolAddress((void**)&att_lo,   g_att_lo);

    cudaFuncSetAttribute(gemm_hmma256<0>, cudaFuncAttributeMaxDynamicSharedMemorySize, G2_SMEM);
    cudaFuncSetAttribute(gemm_hmma256<1>, cudaFuncAttributeMaxDynamicSharedMemorySize, G2_SMEM);
    cudaFuncSetAttribute(gemm_hmma128,    cudaFuncAttributeMaxDynamicSharedMemorySize, G1_SMEM);
    cudaFuncSetAttribute(attn_hmma, cudaFuncAttributeMaxDynamicSharedMemorySize, A_SMEM);

    // conversions
    split_convert<<<(TOK * HID / 4 + 255) / 256, 256>>>(hidden, hid_hi, hid_lo, TOK * HID);
    split_transpose<<<dim3(NQK / 32,  HID / 32), 256>>>(wq, wqkvt_hi, wqkvt_lo, HID, NQK);
    split_transpose<<<dim3(NKVD / 32, HID / 32), 256>>>(
        wk, wqkvt_hi + (size_t)NQK * HID, wqkvt_lo + (size_t)NQK * HID, HID, NKVD);
    split_transpose<<<dim3(NKVD / 32, HID / 32), 256>>>(
        wv, wqkvt_hi + (size_t)(NQK + NKVD) * HID, wqkvt_lo + (size_t)(NQK + NKVD) * HID, HID, NKVD);
    split_transpose<<<dim3(HID / 32, NQK / 32), 256>>>(wo, wot_hi, wot_lo, NQK, HID);

    // fused QKV projection (+concat bias in epilogue), 128x256 tiles
    gemm_hmma256<1><<<dim3(NQKV / 256, TOK / 128), 256, G2_SMEM>>>(
        hid_hi, hid_lo, wqkvt_hi, wqkvt_lo, bq, bk, bv, qkv, NQKV, HID);

    // RoPE + kv_fused output + bf16 splits
    rope_scatter<<<(TOK * 64 + 255) / 256, 256>>>(positions, out_kv);

    // HMMA flash attention (double-buffered KV, masked-warp skip)
    attn_hmma<<<dim3(NQH, SEQL / 128, 4), 256, A_SMEM>>>();

    // o_proj: 128x128 tiles, 2 CTAs/SM (finer wave granularity)
    gemm_hmma128<<<dim3(HID / 128, TOK / 128), 128, G1_SMEM>>>(
        att_hi, att_lo, wot_hi, wot_lo, out, HID, NQK);
}